// round 1
// baseline (speedup 1.0000x reference)
#include <cuda_runtime.h>
#include <math.h>

#define B_    8
#define C_    384
#define HW_   4096
#define HWDIM 64
#define NG_   32
#define CPG_  12
#define KTOP_ 512
#define PI_F  3.14159265358979323846f

// ---------------- scratch (device globals; no allocation) ----------------
__device__ float g_xn[(size_t)B_ * C_ * HW_];
__device__ float g_q [(size_t)B_ * C_ * HW_];   // q -> A -> F4 (reused in place)
__device__ float g_k [(size_t)B_ * C_ * HW_];
__device__ float g_v [(size_t)B_ * C_ * HW_];

// ---------------- GroupNorm ----------------
__global__ __launch_bounds__(256) void groupnorm_kernel(
    const float* __restrict__ x, const float* __restrict__ gamma,
    const float* __restrict__ beta)
{
    int b = blockIdx.x / NG_;
    int g = blockIdx.x % NG_;
    size_t base = ((size_t)b * C_ + (size_t)g * CPG_) * HW_;
    const int n = CPG_ * HW_;  // 49152
    int tid = threadIdx.x;

    float s = 0.f, ss = 0.f;
    for (int i = tid; i < n; i += 256) {
        float v = x[base + i];
        s += v; ss += v * v;
    }
    __shared__ float rs[256], rss[256];
    rs[tid] = s; rss[tid] = ss;
    __syncthreads();
    for (int o = 128; o > 0; o >>= 1) {
        if (tid < o) { rs[tid] += rs[tid + o]; rss[tid] += rss[tid + o]; }
        __syncthreads();
    }
    float mean = rs[0] / (float)n;
    float var  = rss[0] / (float)n - mean * mean;
    float inv  = rsqrtf(var + 1e-5f);

    for (int i = tid; i < n; i += 256) {
        int c = g * CPG_ + i / HW_;
        float v = (x[base + i] - mean) * inv;
        g_xn[base + i] = v * gamma[c] + beta[c];
    }
}

// ---------------- 1x1 conv = per-batch GEMM: Y = W(384x384) * X(384x4096) + b ----------------
// BM=BN=64, BK=16, 256 threads, 4x4 per thread.
template <bool MULXN>
__global__ __launch_bounds__(256) void gemm1x1_kernel(
    const float* __restrict__ Wt, const float* __restrict__ X,
    const float* __restrict__ bias, float* __restrict__ Y)
{
    __shared__ float As[16][64];
    __shared__ float Bs[16][64];

    int b  = blockIdx.z;
    int n0 = blockIdx.x * 64;
    int m0 = blockIdx.y * 64;
    const float* Xb = X + (size_t)b * C_ * HW_;

    int tid = threadIdx.x;
    int tx = tid & 15, ty = tid >> 4;
    int lk = tid >> 4;          // 0..15
    int ln = (tid & 15) * 4;    // 0..60

    float acc[4][4];
#pragma unroll
    for (int i = 0; i < 4; i++)
#pragma unroll
        for (int j = 0; j < 4; j++) acc[i][j] = 0.f;

    for (int k0 = 0; k0 < C_; k0 += 16) {
#pragma unroll
        for (int i = 0; i < 4; i++)
            As[lk][ln + i] = Wt[(size_t)(m0 + ln + i) * C_ + (k0 + lk)];
        *(float4*)&Bs[lk][ln] = *(const float4*)&Xb[(size_t)(k0 + lk) * HW_ + n0 + ln];
        __syncthreads();
#pragma unroll
        for (int k = 0; k < 16; k++) {
            float4 a4 = *(float4*)&As[k][ty * 4];
            float4 b4 = *(float4*)&Bs[k][tx * 4];
            float av[4] = {a4.x, a4.y, a4.z, a4.w};
            float bv[4] = {b4.x, b4.y, b4.z, b4.w};
#pragma unroll
            for (int i = 0; i < 4; i++)
#pragma unroll
                for (int j = 0; j < 4; j++) acc[i][j] += av[i] * bv[j];
        }
        __syncthreads();
    }

    size_t ybase = (size_t)b * C_ * HW_;
#pragma unroll
    for (int i = 0; i < 4; i++) {
        int row = m0 + ty * 4 + i;
        float bi = bias[row];
        size_t off = ybase + (size_t)row * HW_ + n0 + tx * 4;
        float4 o;
        o.x = acc[i][0] + bi; o.y = acc[i][1] + bi;
        o.z = acc[i][2] + bi; o.w = acc[i][3] + bi;
        if (MULXN) {
            float4 m4 = *(const float4*)&g_xn[off];
            o.x *= m4.x; o.y *= m4.y; o.z *= m4.z; o.w *= m4.w;
        }
        *(float4*)&Y[off] = o;
    }
}

// ---------------- 3x3 conv (pad 1) as implicit GEMM, K = 384*9 = 3456 ----------------
__global__ __launch_bounds__(256) void conv3x3_kernel(
    const float* __restrict__ Wt, const float* __restrict__ bias,
    float* __restrict__ Y)
{
    __shared__ float As[16][64];
    __shared__ float Bs[16][64];

    int b  = blockIdx.z;
    int h  = blockIdx.x;          // each block covers one image row (n0 = h*64)
    int m0 = blockIdx.y * 64;
    const float* Xb = g_xn + (size_t)b * C_ * HW_;

    int tid = threadIdx.x;
    int tx = tid & 15, ty = tid >> 4;
    int lk = tid >> 4;
    int ln = (tid & 15) * 4;
    const int KT = C_ * 9;  // 3456

    float acc[4][4];
#pragma unroll
    for (int i = 0; i < 4; i++)
#pragma unroll
        for (int j = 0; j < 4; j++) acc[i][j] = 0.f;

    for (int k0 = 0; k0 < KT; k0 += 16) {
#pragma unroll
        for (int i = 0; i < 4; i++)
            As[lk][ln + i] = Wt[(size_t)(m0 + ln + i) * KT + (k0 + lk)];

        int kk = k0 + lk;
        int ci = kk / 9;
        int rs = kk - ci * 9;
        int dy = rs / 3 - 1;
        int dx = rs - (rs / 3) * 3 - 1;
        int hh = h + dy;
        const float* xrow = Xb + (size_t)ci * HW_ + (size_t)hh * HWDIM;
        bool hok = (hh >= 0 && hh < HWDIM);
#pragma unroll
        for (int i = 0; i < 4; i++) {
            int wv = ln + i + dx;
            float v = 0.f;
            if (hok && wv >= 0 && wv < HWDIM) v = xrow[wv];
            Bs[lk][ln + i] = v;
        }
        __syncthreads();
#pragma unroll
        for (int k = 0; k < 16; k++) {
            float4 a4 = *(float4*)&As[k][ty * 4];
            float4 b4 = *(float4*)&Bs[k][tx * 4];
            float av[4] = {a4.x, a4.y, a4.z, a4.w};
            float bv[4] = {b4.x, b4.y, b4.z, b4.w};
#pragma unroll
            for (int i = 0; i < 4; i++)
#pragma unroll
                for (int j = 0; j < 4; j++) acc[i][j] += av[i] * bv[j];
        }
        __syncthreads();
    }

    size_t ybase = (size_t)b * C_ * HW_;
#pragma unroll
    for (int i = 0; i < 4; i++) {
        int row = m0 + ty * 4 + i;
        float bi = bias[row];
        size_t off = ybase + (size_t)row * HW_ + (size_t)h * HWDIM + tx * 4;
        float4 o;
        o.x = acc[i][0] + bi; o.y = acc[i][1] + bi;
        o.z = acc[i][2] + bi; o.w = acc[i][3] + bi;
        *(float4*)&Y[off] = o;
    }
}

// ---------------- FFT-domain circular conv per (b,c): A = ifft2(fft2(q)*fft2(k)).real ----------------
// 2D DFT as matrix products with the 64x64 DFT matrix F (F symmetric):
//   Fq = F q F ; Fk = F k F ; A = (1/4096) Re( conj(F) (Fq.Fk) conj(F) )
// One block per channel, 512 threads: lane column l = tid&63, 8 rows per thread.
#define FFT_SMEM_FLOATS (128 + 4096 + 3 * 2 * 4096)   // tw + in + T,Fq,Fk complex
#define FFT_SMEM_BYTES  (FFT_SMEM_FLOATS * 4)         // 115200

__global__ __launch_bounds__(512) void fft_attn_kernel(
    float* __restrict__ Aq /* in: q, out: A */, const float* __restrict__ Kk)
{
    extern __shared__ float sm[];
    float2* tw  = (float2*)sm;                        // 64 twiddles
    float*  inb = sm + 128;                           // 4096 real
    float2* T   = (float2*)(sm + 128 + 4096);         // 4096 complex temp
    float2* Fq  = T + 4096;
    float2* Fk  = Fq + 4096;

    int tid = threadIdx.x;
    size_t base = (size_t)blockIdx.x * HW_;
    int l  = tid & 63;
    int jb = (tid >> 6) * 8;

    if (tid < 64) {
        float ang = -2.f * PI_F * (float)tid / 64.f;
        tw[tid] = make_float2(cosf(ang), sinf(ang));
    }
    __syncthreads();

    // ======= two forward transforms: field 0 = q -> Fq, field 1 = k -> Fk =======
    for (int field = 0; field < 2; field++) {
        const float* src = (field == 0) ? (Aq + base) : (Kk + base);
        float2* dst = (field == 0) ? Fq : Fk;

        for (int i = tid; i < 4096; i += 512) inb[i] = src[i];
        __syncthreads();

        // stage A: T[j][l] = sum_m tw[(j*m)&63] * in[m][l]
        {
            float ar[8], ai[8];
#pragma unroll
            for (int jj = 0; jj < 8; jj++) { ar[jj] = 0.f; ai[jj] = 0.f; }
            for (int m = 0; m < 64; m++) {
                float xv = inb[m * 64 + l];
#pragma unroll
                for (int jj = 0; jj < 8; jj++) {
                    float2 c = tw[((jb + jj) * m) & 63];
                    ar[jj] += c.x * xv;
                    ai[jj] += c.y * xv;
                }
            }
#pragma unroll
            for (int jj = 0; jj < 8; jj++)
                T[(jb + jj) * 64 + l] = make_float2(ar[jj], ai[jj]);
        }
        __syncthreads();

        // stage B: dst[j][l] = sum_m T[j][m] * w_l^m (register twiddle rotation)
        {
            float2 wl = tw[l];
            float cr = 1.f, ci = 0.f;
            float ar[8], ai[8];
#pragma unroll
            for (int jj = 0; jj < 8; jj++) { ar[jj] = 0.f; ai[jj] = 0.f; }
            for (int m = 0; m < 64; m++) {
#pragma unroll
                for (int jj = 0; jj < 8; jj++) {
                    float2 t = T[(jb + jj) * 64 + m];
                    ar[jj] += t.x * cr - t.y * ci;
                    ai[jj] += t.x * ci + t.y * cr;
                }
                float nr = cr * wl.x - ci * wl.y;
                ci = cr * wl.y + ci * wl.x;
                cr = nr;
            }
#pragma unroll
            for (int jj = 0; jj < 8; jj++)
                dst[(jb + jj) * 64 + l] = make_float2(ar[jj], ai[jj]);
        }
        __syncthreads();
    }

    // ======= pointwise product P = Fq .* Fk (into Fq) =======
    for (int i = tid; i < 4096; i += 512) {
        float2 a = Fq[i], bq = Fk[i];
        Fq[i] = make_float2(a.x * bq.x - a.y * bq.y, a.x * bq.y + a.y * bq.x);
    }
    __syncthreads();

    // ======= inverse stage 1: T[j][l] = sum_m conj(tw[(j*m)&63]) * P[m][l] =======
    {
        float ar[8], ai[8];
#pragma unroll
        for (int jj = 0; jj < 8; jj++) { ar[jj] = 0.f; ai[jj] = 0.f; }
        for (int m = 0; m < 64; m++) {
            float2 p = Fq[m * 64 + l];
#pragma unroll
            for (int jj = 0; jj < 8; jj++) {
                float2 c = tw[((jb + jj) * m) & 63];
                // conj(c) * p
                ar[jj] += c.x * p.x + c.y * p.y;
                ai[jj] += c.x * p.y - c.y * p.x;
            }
        }
#pragma unroll
        for (int jj = 0; jj < 8; jj++)
            T[(jb + jj) * 64 + l] = make_float2(ar[jj], ai[jj]);
    }
    __syncthreads();

    // ======= inverse stage 2 (real part only): A[j][l] = (1/4096) sum_m Re(T[j][m] * conj(w_l^m)) =======
    {
        float2 wl = tw[l];
        float cr = 1.f, ci = 0.f;
        float ar[8];
#pragma unroll
        for (int jj = 0; jj < 8; jj++) ar[jj] = 0.f;
        for (int m = 0; m < 64; m++) {
#pragma unroll
            for (int jj = 0; jj < 8; jj++) {
                float2 t = T[(jb + jj) * 64 + m];
                ar[jj] += t.x * cr + t.y * ci;   // Re(t * conj(cur))
            }
            float nr = cr * wl.x - ci * wl.y;
            ci = cr * wl.y + ci * wl.x;
            cr = nr;
        }
#pragma unroll
        for (int jj = 0; jj < 8; jj++)
            Aq[base + (size_t)(jb + jj) * 64 + l] = ar[jj] * (1.f / 4096.f);
    }
}

// ---------------- top-k(512) threshold + masked softmax + multiply by v ----------------
__device__ __forceinline__ unsigned f2ord(float f) {
    unsigned b = __float_as_uint(f);
    return (b & 0x80000000u) ? ~b : (b | 0x80000000u);
}
__device__ __forceinline__ float ord2f(unsigned u) {
    unsigned b = (u & 0x80000000u) ? (u ^ 0x80000000u) : ~u;
    return __uint_as_float(b);
}

__global__ __launch_bounds__(256) void topk_softmax_kernel(
    float* __restrict__ A /* in: A, out: F4 */, const float* __restrict__ V)
{
    __shared__ unsigned ua[4096];
    __shared__ unsigned hist[256];
    __shared__ float redf[256];
    __shared__ unsigned s_prefix;
    __shared__ int s_kk;
    __shared__ float s_maxf;

    int tid = threadIdx.x;
    size_t base = (size_t)blockIdx.x * HW_;

    unsigned mymax = 0u;
    for (int i = tid; i < 4096; i += 256) {
        unsigned u = f2ord(A[base + i]);
        ua[i] = u;
        mymax = max(mymax, u);
    }
    hist[tid] = mymax;
    __syncthreads();
    for (int o = 128; o > 0; o >>= 1) {
        if (tid < o) hist[tid] = max(hist[tid], hist[tid + o]);
        __syncthreads();
    }
    if (tid == 0) {
        s_maxf = ord2f(hist[0]);
        s_kk = KTOP_;
        s_prefix = 0u;
    }
    __syncthreads();

    // 4-pass radix select (descending), MSB first
    for (int level = 3; level >= 0; level--) {
        hist[tid] = 0u;
        __syncthreads();
        int shift = level * 8;
        unsigned maskhi = (level == 3) ? 0u : (0xFFFFFFFFu << (shift + 8));
        unsigned prefix = s_prefix;
        for (int i = tid; i < 4096; i += 256) {
            unsigned u = ua[i];
            if ((u & maskhi) == prefix)
                atomicAdd(&hist[(u >> shift) & 255], 1u);
        }
        __syncthreads();
        if (tid == 0) {
            int kk = s_kk;
            unsigned cum = 0;
            int d = 255;
            for (; d >= 0; d--) {
                unsigned c = hist[d];
                if (cum + c >= (unsigned)kk) break;
                cum += c;
            }
            if (d < 0) d = 0;   // safety
            s_kk = kk - (int)cum;
            s_prefix = prefix | ((unsigned)d << shift);
        }
        __syncthreads();
    }

    unsigned thr = s_prefix;   // ordered-uint value of the k-th largest
    float maxf = s_maxf;

    float ssum = 0.f;
    for (int i = tid; i < 4096; i += 256) {
        unsigned u = ua[i];
        if (u >= thr) ssum += expf(ord2f(u) - maxf);
    }
    redf[tid] = ssum;
    __syncthreads();
    for (int o = 128; o > 0; o >>= 1) {
        if (tid < o) redf[tid] += redf[tid + o];
        __syncthreads();
    }
    float inv = 1.f / redf[0];

    for (int i = tid; i < 4096; i += 256) {
        unsigned u = ua[i];
        float o = 0.f;
        if (u >= thr) o = V[base + i] * expf(ord2f(u) - maxf) * inv;
        A[base + i] = o;
    }
}

// ---------------- launch ----------------
extern "C" void kernel_launch(void* const* d_in, const int* in_sizes, int n_in,
                              void* d_out, int out_size)
{
    const float* x     = (const float*)d_in[0];
    const float* gamma = (const float*)d_in[1];
    const float* beta  = (const float*)d_in[2];
    const float* wq    = (const float*)d_in[3];
    const float* bq    = (const float*)d_in[4];
    const float* wk    = (const float*)d_in[5];
    const float* bk    = (const float*)d_in[6];
    const float* wv    = (const float*)d_in[7];
    const float* bv    = (const float*)d_in[8];
    const float* wf    = (const float*)d_in[9];
    const float* bf    = (const float*)d_in[10];
    float* out = (float*)d_out;

    void *pxn, *pq, *pk, *pv;
    cudaGetSymbolAddress(&pxn, g_xn);
    cudaGetSymbolAddress(&pq,  g_q);
    cudaGetSymbolAddress(&pk,  g_k);
    cudaGetSymbolAddress(&pv,  g_v);

    cudaFuncSetAttribute(fft_attn_kernel,
                         cudaFuncAttributeMaxDynamicSharedMemorySize, FFT_SMEM_BYTES);

    // 1. GroupNorm
    groupnorm_kernel<<<B_ * NG_, 256>>>(x, gamma, beta);

    // 2-4. q / v (1x1) and k (3x3) projections
    dim3 gg(HW_ / 64, C_ / 64, B_);
    gemm1x1_kernel<false><<<gg, 256>>>(wq, (const float*)pxn, bq, (float*)pq);
    gemm1x1_kernel<false><<<gg, 256>>>(wv, (const float*)pxn, bv, (float*)pv);
    conv3x3_kernel<<<gg, 256>>>(wk, bk, (float*)pk);

    // 5. FFT circular conv: A (into g_q)
    fft_attn_kernel<<<B_ * C_, 512, FFT_SMEM_BYTES>>>((float*)pq, (const float*)pk);

    // 6. top-k + softmax + v-multiply: F4 (into g_q)
    topk_softmax_kernel<<<B_ * C_, 256>>>((float*)pq, (const float*)pv);

    // 7. final 1x1 conv with xn-multiply epilogue
    gemm1x1_kernel<true><<<gg, 256>>>(wf, (const float*)pq, bf, out);
}

// round 2
// speedup vs baseline: 1.2729x; 1.2729x over previous
#include <cuda_runtime.h>
#include <math.h>

#define B_    8
#define C_    384
#define HW_   4096
#define HWDIM 64
#define NG_   32
#define CPG_  12
#define KTOP_ 512
#define PI_F  3.14159265358979323846f

// ---------------- scratch (device globals; no allocation) ----------------
__device__ float g_xn[(size_t)B_ * C_ * HW_];
__device__ float g_q [(size_t)B_ * C_ * HW_];   // q -> A -> F4 (reused in place)
__device__ float g_k [(size_t)B_ * C_ * HW_];
__device__ float g_v [(size_t)B_ * C_ * HW_];

// ---------------- GroupNorm ----------------
__global__ __launch_bounds__(256) void groupnorm_kernel(
    const float* __restrict__ x, const float* __restrict__ gamma,
    const float* __restrict__ beta)
{
    int b = blockIdx.x / NG_;
    int g = blockIdx.x % NG_;
    size_t base = ((size_t)b * C_ + (size_t)g * CPG_) * HW_;
    const int n = CPG_ * HW_;  // 49152
    int tid = threadIdx.x;

    float s = 0.f, ss = 0.f;
    for (int i = tid; i < n; i += 256) {
        float v = x[base + i];
        s += v; ss += v * v;
    }
    __shared__ float rs[256], rss[256];
    rs[tid] = s; rss[tid] = ss;
    __syncthreads();
    for (int o = 128; o > 0; o >>= 1) {
        if (tid < o) { rs[tid] += rs[tid + o]; rss[tid] += rss[tid + o]; }
        __syncthreads();
    }
    float mean = rs[0] / (float)n;
    float var  = rss[0] / (float)n - mean * mean;
    float inv  = rsqrtf(var + 1e-5f);

    for (int i = tid; i < n; i += 256) {
        int c = g * CPG_ + i / HW_;
        float v = (x[base + i] - mean) * inv;
        g_xn[base + i] = v * gamma[c] + beta[c];
    }
}

// ---------------- unified 128x128x8 SGEMM (double buffered, 8x8/thread) ----------------
// Y[b, m, n] = sum_k Wt[m, k] * B(k, n) + bias[m]   (per batch b)
//   CONV3=false: B(k,n) = X[b, k, n]                        (KTOT = 384)
//   CONV3=true : B(k,n) = xn[b, ci, h+dy, w+dx] implicit    (KTOT = 3456)
//   MULXN: multiply output by g_xn elementwise (final conv epilogue)
template <int KTOT, bool CONV3, bool MULXN>
__global__ __launch_bounds__(256) void gemm128_kernel(
    const float* __restrict__ Wt, const float* __restrict__ X,
    const float* __restrict__ bias, float* __restrict__ Y)
{
    __shared__ float As[2][8][128];
    __shared__ float Bs[2][8][128];

    const int b  = blockIdx.z;
    const int n0 = blockIdx.x * 128;
    const int m0 = blockIdx.y * 128;
    const float* Xb = X + (size_t)b * C_ * HW_;

    const int tid = threadIdx.x;
    // A-load mapping: 128 rows x 8 k, one float4 per thread along K
    const int am = tid >> 1;
    const int ak = (tid & 1) * 4;
    // B-load mapping: 8 k x 128 n, one float4 per thread along N
    const int bk = tid >> 5;
    const int bn = (tid & 31) * 4;
    // compute mapping
    const int tx = tid & 15;
    const int ty = tid >> 4;

    float acc[8][8];
#pragma unroll
    for (int i = 0; i < 8; i++)
#pragma unroll
        for (int j = 0; j < 8; j++) acc[i][j] = 0.f;

    const int NIT = KTOT / 8;

    float4 aReg, bReg;

    // ---- prologue: load tile 0 into registers ----
    aReg = *(const float4*)&Wt[(size_t)(m0 + am) * KTOT + ak];
    if (!CONV3) {
        bReg = *(const float4*)&Xb[(size_t)bk * HW_ + n0 + bn];
    } else {
        int kk = bk;
        int ci = kk / 9;
        int rs = kk - ci * 9;
        int dy = rs / 3 - 1, dx = rs - (rs / 3) * 3 - 1;
        float bv[4];
#pragma unroll
        for (int j = 0; j < 4; j++) {
            int n = n0 + bn + j;
            int h = (n >> 6) + dy;
            int w = (n & 63) + dx;
            bv[j] = (h >= 0 && h < HWDIM && w >= 0 && w < HWDIM)
                        ? Xb[(size_t)ci * HW_ + h * HWDIM + w] : 0.f;
        }
        bReg = make_float4(bv[0], bv[1], bv[2], bv[3]);
    }
    // store into buffer 0
    As[0][ak + 0][am] = aReg.x; As[0][ak + 1][am] = aReg.y;
    As[0][ak + 2][am] = aReg.z; As[0][ak + 3][am] = aReg.w;
    *(float4*)&Bs[0][bk][bn] = bReg;
    __syncthreads();

    for (int it = 0; it < NIT; it++) {
        const int p = it & 1;
        // ---- issue next tile's global loads early ----
        if (it + 1 < NIT) {
            const int k0 = (it + 1) * 8;
            aReg = *(const float4*)&Wt[(size_t)(m0 + am) * KTOT + k0 + ak];
            if (!CONV3) {
                bReg = *(const float4*)&Xb[(size_t)(k0 + bk) * HW_ + n0 + bn];
            } else {
                int kk = k0 + bk;
                int ci = kk / 9;
                int rs = kk - ci * 9;
                int dy = rs / 3 - 1, dx = rs - (rs / 3) * 3 - 1;
                float bv[4];
#pragma unroll
                for (int j = 0; j < 4; j++) {
                    int n = n0 + bn + j;
                    int h = (n >> 6) + dy;
                    int w = (n & 63) + dx;
                    bv[j] = (h >= 0 && h < HWDIM && w >= 0 && w < HWDIM)
                                ? Xb[(size_t)ci * HW_ + h * HWDIM + w] : 0.f;
                }
                bReg = make_float4(bv[0], bv[1], bv[2], bv[3]);
            }
        }
        // ---- compute from buffer p ----
#pragma unroll
        for (int k = 0; k < 8; k++) {
            float4 a0 = *(float4*)&As[p][k][ty * 8];
            float4 a1 = *(float4*)&As[p][k][ty * 8 + 4];
            float4 b0 = *(float4*)&Bs[p][k][tx * 8];
            float4 b1 = *(float4*)&Bs[p][k][tx * 8 + 4];
            float av[8] = {a0.x, a0.y, a0.z, a0.w, a1.x, a1.y, a1.z, a1.w};
            float bw[8] = {b0.x, b0.y, b0.z, b0.w, b1.x, b1.y, b1.z, b1.w};
#pragma unroll
            for (int i = 0; i < 8; i++)
#pragma unroll
                for (int j = 0; j < 8; j++) acc[i][j] += av[i] * bw[j];
        }
        // ---- store next tile into the other buffer ----
        if (it + 1 < NIT) {
            const int q = 1 - p;
            As[q][ak + 0][am] = aReg.x; As[q][ak + 1][am] = aReg.y;
            As[q][ak + 2][am] = aReg.z; As[q][ak + 3][am] = aReg.w;
            *(float4*)&Bs[q][bk][bn] = bReg;
        }
        __syncthreads();
    }

    // ---- epilogue ----
    const size_t ybase = (size_t)b * C_ * HW_;
#pragma unroll
    for (int i = 0; i < 8; i++) {
        int row = m0 + ty * 8 + i;
        float bi = bias[row];
        size_t off = ybase + (size_t)row * HW_ + n0 + tx * 8;
#pragma unroll
        for (int jq = 0; jq < 2; jq++) {
            float4 o;
            o.x = acc[i][jq * 4 + 0] + bi;
            o.y = acc[i][jq * 4 + 1] + bi;
            o.z = acc[i][jq * 4 + 2] + bi;
            o.w = acc[i][jq * 4 + 3] + bi;
            if (MULXN) {
                float4 m4 = *(const float4*)&g_xn[off + jq * 4];
                o.x *= m4.x; o.y *= m4.y; o.z *= m4.z; o.w *= m4.w;
            }
            *(float4*)&Y[off + jq * 4] = o;
        }
    }
}

// ---------------- FFT-domain circular conv per (b,c): A = ifft2(fft2(q)*fft2(k)).real ----------------
#define FFT_SMEM_FLOATS (128 + 4096 + 3 * 2 * 4096)
#define FFT_SMEM_BYTES  (FFT_SMEM_FLOATS * 4)   // 115200

__global__ __launch_bounds__(512) void fft_attn_kernel(
    float* __restrict__ Aq /* in: q, out: A */, const float* __restrict__ Kk)
{
    extern __shared__ float sm[];
    float2* tw  = (float2*)sm;
    float*  inb = sm + 128;
    float2* T   = (float2*)(sm + 128 + 4096);
    float2* Fq  = T + 4096;
    float2* Fk  = Fq + 4096;

    int tid = threadIdx.x;
    size_t base = (size_t)blockIdx.x * HW_;
    int l  = tid & 63;
    int jb = (tid >> 6) * 8;

    if (tid < 64) {
        float ang = -2.f * PI_F * (float)tid / 64.f;
        tw[tid] = make_float2(cosf(ang), sinf(ang));
    }
    __syncthreads();

    for (int field = 0; field < 2; field++) {
        const float* src = (field == 0) ? (Aq + base) : (Kk + base);
        float2* dst = (field == 0) ? Fq : Fk;

        for (int i = tid; i < 4096; i += 512) inb[i] = src[i];
        __syncthreads();

        {
            float ar[8], ai[8];
#pragma unroll
            for (int jj = 0; jj < 8; jj++) { ar[jj] = 0.f; ai[jj] = 0.f; }
            for (int m = 0; m < 64; m++) {
                float xv = inb[m * 64 + l];
#pragma unroll
                for (int jj = 0; jj < 8; jj++) {
                    float2 c = tw[((jb + jj) * m) & 63];
                    ar[jj] += c.x * xv;
                    ai[jj] += c.y * xv;
                }
            }
#pragma unroll
            for (int jj = 0; jj < 8; jj++)
                T[(jb + jj) * 64 + l] = make_float2(ar[jj], ai[jj]);
        }
        __syncthreads();

        {
            float2 wl = tw[l];
            float cr = 1.f, ci = 0.f;
            float ar[8], ai[8];
#pragma unroll
            for (int jj = 0; jj < 8; jj++) { ar[jj] = 0.f; ai[jj] = 0.f; }
            for (int m = 0; m < 64; m++) {
#pragma unroll
                for (int jj = 0; jj < 8; jj++) {
                    float2 t = T[(jb + jj) * 64 + m];
                    ar[jj] += t.x * cr - t.y * ci;
                    ai[jj] += t.x * ci + t.y * cr;
                }
                float nr = cr * wl.x - ci * wl.y;
                ci = cr * wl.y + ci * wl.x;
                cr = nr;
            }
#pragma unroll
            for (int jj = 0; jj < 8; jj++)
                dst[(jb + jj) * 64 + l] = make_float2(ar[jj], ai[jj]);
        }
        __syncthreads();
    }

    for (int i = tid; i < 4096; i += 512) {
        float2 a = Fq[i], bq = Fk[i];
        Fq[i] = make_float2(a.x * bq.x - a.y * bq.y, a.x * bq.y + a.y * bq.x);
    }
    __syncthreads();

    {
        float ar[8], ai[8];
#pragma unroll
        for (int jj = 0; jj < 8; jj++) { ar[jj] = 0.f; ai[jj] = 0.f; }
        for (int m = 0; m < 64; m++) {
            float2 p = Fq[m * 64 + l];
#pragma unroll
            for (int jj = 0; jj < 8; jj++) {
                float2 c = tw[((jb + jj) * m) & 63];
                ar[jj] += c.x * p.x + c.y * p.y;
                ai[jj] += c.x * p.y - c.y * p.x;
            }
        }
#pragma unroll
        for (int jj = 0; jj < 8; jj++)
            T[(jb + jj) * 64 + l] = make_float2(ar[jj], ai[jj]);
    }
    __syncthreads();

    {
        float2 wl = tw[l];
        float cr = 1.f, ci = 0.f;
        float ar[8];
#pragma unroll
        for (int jj = 0; jj < 8; jj++) ar[jj] = 0.f;
        for (int m = 0; m < 64; m++) {
#pragma unroll
            for (int jj = 0; jj < 8; jj++) {
                float2 t = T[(jb + jj) * 64 + m];
                ar[jj] += t.x * cr + t.y * ci;
            }
            float nr = cr * wl.x - ci * wl.y;
            ci = cr * wl.y + ci * wl.x;
            cr = nr;
        }
#pragma unroll
        for (int jj = 0; jj < 8; jj++)
            Aq[base + (size_t)(jb + jj) * 64 + l] = ar[jj] * (1.f / 4096.f);
    }
}

// ---------------- top-k(512) threshold + masked softmax + multiply by v ----------------
__device__ __forceinline__ unsigned f2ord(float f) {
    unsigned b = __float_as_uint(f);
    return (b & 0x80000000u) ? ~b : (b | 0x80000000u);
}
__device__ __forceinline__ float ord2f(unsigned u) {
    unsigned b = (u & 0x80000000u) ? (u ^ 0x80000000u) : ~u;
    return __uint_as_float(b);
}

__global__ __launch_bounds__(256) void topk_softmax_kernel(
    float* __restrict__ A, const float* __restrict__ V)
{
    __shared__ unsigned ua[4096];
    __shared__ unsigned hist[256];
    __shared__ float redf[256];
    __shared__ unsigned s_prefix;
    __shared__ int s_kk;
    __shared__ float s_maxf;

    int tid = threadIdx.x;
    size_t base = (size_t)blockIdx.x * HW_;

    unsigned mymax = 0u;
    for (int i = tid; i < 4096; i += 256) {
        unsigned u = f2ord(A[base + i]);
        ua[i] = u;
        mymax = max(mymax, u);
    }
    hist[tid] = mymax;
    __syncthreads();
    for (int o = 128; o > 0; o >>= 1) {
        if (tid < o) hist[tid] = max(hist[tid], hist[tid + o]);
        __syncthreads();
    }
    if (tid == 0) {
        s_maxf = ord2f(hist[0]);
        s_kk = KTOP_;
        s_prefix = 0u;
    }
    __syncthreads();

    for (int level = 3; level >= 0; level--) {
        hist[tid] = 0u;
        __syncthreads();
        int shift = level * 8;
        unsigned maskhi = (level == 3) ? 0u : (0xFFFFFFFFu << (shift + 8));
        unsigned prefix = s_prefix;
        for (int i = tid; i < 4096; i += 256) {
            unsigned u = ua[i];
            if ((u & maskhi) == prefix)
                atomicAdd(&hist[(u >> shift) & 255], 1u);
        }
        __syncthreads();
        if (tid == 0) {
            int kk = s_kk;
            unsigned cum = 0;
            int d = 255;
            for (; d >= 0; d--) {
                unsigned c = hist[d];
                if (cum + c >= (unsigned)kk) break;
                cum += c;
            }
            if (d < 0) d = 0;
            s_kk = kk - (int)cum;
            s_prefix = prefix | ((unsigned)d << shift);
        }
        __syncthreads();
    }

    unsigned thr = s_prefix;
    float maxf = s_maxf;

    float ssum = 0.f;
    for (int i = tid; i < 4096; i += 256) {
        unsigned u = ua[i];
        if (u >= thr) ssum += expf(ord2f(u) - maxf);
    }
    redf[tid] = ssum;
    __syncthreads();
    for (int o = 128; o > 0; o >>= 1) {
        if (tid < o) redf[tid] += redf[tid + o];
        __syncthreads();
    }
    float inv = 1.f / redf[0];

    for (int i = tid; i < 4096; i += 256) {
        unsigned u = ua[i];
        float o = 0.f;
        if (u >= thr) o = V[base + i] * expf(ord2f(u) - maxf) * inv;
        A[base + i] = o;
    }
}

// ---------------- launch ----------------
extern "C" void kernel_launch(void* const* d_in, const int* in_sizes, int n_in,
                              void* d_out, int out_size)
{
    const float* x     = (const float*)d_in[0];
    const float* gamma = (const float*)d_in[1];
    const float* beta  = (const float*)d_in[2];
    const float* wq    = (const float*)d_in[3];
    const float* bq    = (const float*)d_in[4];
    const float* wk    = (const float*)d_in[5];
    const float* bk    = (const float*)d_in[6];
    const float* wv    = (const float*)d_in[7];
    const float* bv    = (const float*)d_in[8];
    const float* wf    = (const float*)d_in[9];
    const float* bf    = (const float*)d_in[10];
    float* out = (float*)d_out;

    void *pxn, *pq, *pk, *pv;
    cudaGetSymbolAddress(&pxn, g_xn);
    cudaGetSymbolAddress(&pq,  g_q);
    cudaGetSymbolAddress(&pk,  g_k);
    cudaGetSymbolAddress(&pv,  g_v);

    cudaFuncSetAttribute(fft_attn_kernel,
                         cudaFuncAttributeMaxDynamicSharedMemorySize, FFT_SMEM_BYTES);

    // 1. GroupNorm
    groupnorm_kernel<<<B_ * NG_, 256>>>(x, gamma, beta);

    // 2-4. q / v (1x1) and k (3x3) projections
    dim3 gg(HW_ / 128, C_ / 128, B_);
    gemm128_kernel<C_,     false, false><<<gg, 256>>>(wq, (const float*)pxn, bq, (float*)pq);
    gemm128_kernel<C_,     false, false><<<gg, 256>>>(wv, (const float*)pxn, bv, (float*)pv);
    gemm128_kernel<C_ * 9, true,  false><<<gg, 256>>>(wk, (const float*)pxn, bk, (float*)pk);

    // 5. FFT circular conv: A (into g_q)
    fft_attn_kernel<<<B_ * C_, 512, FFT_SMEM_BYTES>>>((float*)pq, (const float*)pk);

    // 6. top-k + softmax + v-multiply: F4 (into g_q)
    topk_softmax_kernel<<<B_ * C_, 256>>>((float*)pq, (const float*)pv);

    // 7. final 1x1 conv with xn-multiply epilogue
    gemm128_kernel<C_,     false, true ><<<gg, 256>>>(wf, (const float*)pq, bf, out);
}

// round 3
// speedup vs baseline: 1.6126x; 1.2669x over previous
#include <cuda_runtime.h>
#include <math.h>

#define B_    8
#define C_    384
#define HW_   4096
#define HWDIM 64
#define NG_   32
#define CPG_  12
#define KTOP_ 512
#define PI_F  3.14159265358979323846f

// ---------------- scratch (device globals; no allocation) ----------------
__device__ float g_xn[(size_t)B_ * C_ * HW_];
__device__ float g_q [(size_t)B_ * C_ * HW_];   // q -> A -> F4 (reused in place)
__device__ float g_k [(size_t)B_ * C_ * HW_];
__device__ float g_v [(size_t)B_ * C_ * HW_];

// ---------------- GroupNorm ----------------
__global__ __launch_bounds__(256) void groupnorm_kernel(
    const float* __restrict__ x, const float* __restrict__ gamma,
    const float* __restrict__ beta)
{
    int b = blockIdx.x / NG_;
    int g = blockIdx.x % NG_;
    size_t base = ((size_t)b * C_ + (size_t)g * CPG_) * HW_;
    const int n = CPG_ * HW_;  // 49152
    int tid = threadIdx.x;

    float s = 0.f, ss = 0.f;
    for (int i = tid; i < n; i += 256) {
        float v = x[base + i];
        s += v; ss += v * v;
    }
    __shared__ float rs[256], rss[256];
    rs[tid] = s; rss[tid] = ss;
    __syncthreads();
    for (int o = 128; o > 0; o >>= 1) {
        if (tid < o) { rs[tid] += rs[tid + o]; rss[tid] += rss[tid + o]; }
        __syncthreads();
    }
    float mean = rs[0] / (float)n;
    float var  = rss[0] / (float)n - mean * mean;
    float inv  = rsqrtf(var + 1e-5f);

    for (int i = tid; i < n; i += 256) {
        int c = g * CPG_ + i / HW_;
        float v = (x[base + i] - mean) * inv;
        g_xn[base + i] = v * gamma[c] + beta[c];
    }
}

// ---------------- tf32 helpers ----------------
__device__ __forceinline__ float tf32_round(float x) {
    unsigned r;
    asm("cvt.rna.tf32.f32 %0, %1;" : "=r"(r) : "f"(x));
    return __uint_as_float(r);
}

__device__ __forceinline__ void mma_tf32(
    float* c, unsigned a0, unsigned a1, unsigned a2, unsigned a3,
    unsigned b0, unsigned b1)
{
    asm volatile(
        "mma.sync.aligned.m16n8k8.row.col.f32.tf32.tf32.f32 "
        "{%0,%1,%2,%3}, {%4,%5,%6,%7}, {%8,%9}, {%0,%1,%2,%3};"
        : "+f"(c[0]), "+f"(c[1]), "+f"(c[2]), "+f"(c[3])
        : "r"(a0), "r"(a1), "r"(a2), "r"(a3), "r"(b0), "r"(b1));
}

// ---------------- tensor-core SGEMM via split-tf32 (hi+lo, 3 MMAs) ----------------
// Y[b, m, n] = sum_k Wt[m,k] * B(k,n) + bias[m]
//   CONV3=false: B(k,n) = X[b,k,n]                     (KTOT = 384)
//   CONV3=true : B(k,n) = xn[b,ci,h+dy,w+dx] implicit  (KTOT = 3456)
//   MULXN: multiply output by g_xn elementwise
// 128x128 block tile, BK=8, 256 threads = 8 warps (2m x 4n), warp tile 64x32.
#define SA_ 136   // padded smem row stride (floats): banks (8t+g)%32 all distinct

template <int KTOT, bool CONV3, bool MULXN>
__global__ __launch_bounds__(256) void gemm_tc_kernel(
    const float* __restrict__ Wt, const float* __restrict__ X,
    const float* __restrict__ bias, float* __restrict__ Y)
{
    __shared__ float Ah[2][8][SA_];
    __shared__ float Al[2][8][SA_];
    __shared__ float Bh[2][8][SA_];
    __shared__ float Bl[2][8][SA_];

    const int b  = blockIdx.z;
    const int n0 = blockIdx.x * 128;
    const int m0 = blockIdx.y * 128;
    const float* Xb = X + (size_t)b * C_ * HW_;

    const int tid  = threadIdx.x;
    const int lane = tid & 31;
    const int wid  = tid >> 5;
    const int wm   = wid & 1;        // 0..1 -> 64-row slab
    const int wn   = wid >> 1;       // 0..3 -> 32-col slab
    const int g    = lane >> 2;      // group id 0..7
    const int t    = lane & 3;       // thread-in-group 0..3

    // global load mapping
    const int am = tid >> 1;          // 0..127
    const int ak = (tid & 1) * 4;     // 0 or 4
    const int bk = tid >> 5;          // 0..7
    const int bn = (tid & 31) * 4;    // 0..124

    float acc[4][4][4];
#pragma unroll
    for (int mi = 0; mi < 4; mi++)
#pragma unroll
        for (int ni = 0; ni < 4; ni++)
#pragma unroll
            for (int r = 0; r < 4; r++) acc[mi][ni][r] = 0.f;

    const int NIT = KTOT / 8;
    float4 aReg, bReg;

    // ---- prologue ----
    aReg = *(const float4*)&Wt[(size_t)(m0 + am) * KTOT + ak];
    if (!CONV3) {
        bReg = *(const float4*)&Xb[(size_t)bk * HW_ + n0 + bn];
    } else {
        int kk = bk, ci = kk / 9, rs = kk - ci * 9;
        int dy = rs / 3 - 1, dx = rs - (rs / 3) * 3 - 1;
        float bv[4];
#pragma unroll
        for (int j = 0; j < 4; j++) {
            int n = n0 + bn + j;
            int h = (n >> 6) + dy, w = (n & 63) + dx;
            bv[j] = (h >= 0 && h < HWDIM && w >= 0 && w < HWDIM)
                        ? Xb[(size_t)ci * HW_ + h * HWDIM + w] : 0.f;
        }
        bReg = make_float4(bv[0], bv[1], bv[2], bv[3]);
    }
    {
        float av[4] = {aReg.x, aReg.y, aReg.z, aReg.w};
#pragma unroll
        for (int j = 0; j < 4; j++) {
            float hi = tf32_round(av[j]);
            Ah[0][ak + j][am] = hi;
            Al[0][ak + j][am] = tf32_round(av[j] - hi);
        }
        float bv[4] = {bReg.x, bReg.y, bReg.z, bReg.w};
        float4 h4, l4;
        float* hp = (float*)&h4; float* lp = (float*)&l4;
#pragma unroll
        for (int j = 0; j < 4; j++) {
            hp[j] = tf32_round(bv[j]);
            lp[j] = tf32_round(bv[j] - hp[j]);
        }
        *(float4*)&Bh[0][bk][bn] = h4;
        *(float4*)&Bl[0][bk][bn] = l4;
    }
    __syncthreads();

    for (int it = 0; it < NIT; it++) {
        const int p = it & 1;
        // ---- prefetch next tile ----
        if (it + 1 < NIT) {
            const int k0 = (it + 1) * 8;
            aReg = *(const float4*)&Wt[(size_t)(m0 + am) * KTOT + k0 + ak];
            if (!CONV3) {
                bReg = *(const float4*)&Xb[(size_t)(k0 + bk) * HW_ + n0 + bn];
            } else {
                int kk = k0 + bk, ci = kk / 9, rs = kk - ci * 9;
                int dy = rs / 3 - 1, dx = rs - (rs / 3) * 3 - 1;
                float bv[4];
#pragma unroll
                for (int j = 0; j < 4; j++) {
                    int n = n0 + bn + j;
                    int h = (n >> 6) + dy, w = (n & 63) + dx;
                    bv[j] = (h >= 0 && h < HWDIM && w >= 0 && w < HWDIM)
                                ? Xb[(size_t)ci * HW_ + h * HWDIM + w] : 0.f;
                }
                bReg = make_float4(bv[0], bv[1], bv[2], bv[3]);
            }
        }

        // ---- load fragments from smem ----
        unsigned ah[4][4], al[4][4], bh[4][2], bl[4][2];
#pragma unroll
        for (int mi = 0; mi < 4; mi++) {
            const int mb = wm * 64 + mi * 16 + g;
            ah[mi][0] = __float_as_uint(Ah[p][t    ][mb    ]);
            ah[mi][1] = __float_as_uint(Ah[p][t    ][mb + 8]);
            ah[mi][2] = __float_as_uint(Ah[p][t + 4][mb    ]);
            ah[mi][3] = __float_as_uint(Ah[p][t + 4][mb + 8]);
            al[mi][0] = __float_as_uint(Al[p][t    ][mb    ]);
            al[mi][1] = __float_as_uint(Al[p][t    ][mb + 8]);
            al[mi][2] = __float_as_uint(Al[p][t + 4][mb    ]);
            al[mi][3] = __float_as_uint(Al[p][t + 4][mb + 8]);
        }
#pragma unroll
        for (int ni = 0; ni < 4; ni++) {
            const int nb = wn * 32 + ni * 8 + g;
            bh[ni][0] = __float_as_uint(Bh[p][t    ][nb]);
            bh[ni][1] = __float_as_uint(Bh[p][t + 4][nb]);
            bl[ni][0] = __float_as_uint(Bl[p][t    ][nb]);
            bl[ni][1] = __float_as_uint(Bl[p][t + 4][nb]);
        }

        // ---- 3-term split MMAs ----
#pragma unroll
        for (int mi = 0; mi < 4; mi++)
#pragma unroll
            for (int ni = 0; ni < 4; ni++) {
                mma_tf32(acc[mi][ni], ah[mi][0], ah[mi][1], ah[mi][2], ah[mi][3],
                         bh[ni][0], bh[ni][1]);
                mma_tf32(acc[mi][ni], ah[mi][0], ah[mi][1], ah[mi][2], ah[mi][3],
                         bl[ni][0], bl[ni][1]);
                mma_tf32(acc[mi][ni], al[mi][0], al[mi][1], al[mi][2], al[mi][3],
                         bh[ni][0], bh[ni][1]);
            }

        // ---- store next tile ----
        if (it + 1 < NIT) {
            const int q = 1 - p;
            float av[4] = {aReg.x, aReg.y, aReg.z, aReg.w};
#pragma unroll
            for (int j = 0; j < 4; j++) {
                float hi = tf32_round(av[j]);
                Ah[q][ak + j][am] = hi;
                Al[q][ak + j][am] = tf32_round(av[j] - hi);
            }
            float bv[4] = {bReg.x, bReg.y, bReg.z, bReg.w};
            float4 h4, l4;
            float* hp = (float*)&h4; float* lp = (float*)&l4;
#pragma unroll
            for (int j = 0; j < 4; j++) {
                hp[j] = tf32_round(bv[j]);
                lp[j] = tf32_round(bv[j] - hp[j]);
            }
            *(float4*)&Bh[q][bk][bn] = h4;
            *(float4*)&Bl[q][bk][bn] = l4;
        }
        __syncthreads();
    }

    // ---- epilogue ----
    const size_t ybase = (size_t)b * C_ * HW_;
#pragma unroll
    for (int mi = 0; mi < 4; mi++) {
        const int r0 = m0 + wm * 64 + mi * 16 + g;
        const int r1 = r0 + 8;
        const float bi0 = bias[r0];
        const float bi1 = bias[r1];
#pragma unroll
        for (int ni = 0; ni < 4; ni++) {
            const int col = n0 + wn * 32 + ni * 8 + 2 * t;
            float2 o0 = make_float2(acc[mi][ni][0] + bi0, acc[mi][ni][1] + bi0);
            float2 o1 = make_float2(acc[mi][ni][2] + bi1, acc[mi][ni][3] + bi1);
            size_t off0 = ybase + (size_t)r0 * HW_ + col;
            size_t off1 = ybase + (size_t)r1 * HW_ + col;
            if (MULXN) {
                float2 m0v = *(const float2*)&g_xn[off0];
                float2 m1v = *(const float2*)&g_xn[off1];
                o0.x *= m0v.x; o0.y *= m0v.y;
                o1.x *= m1v.x; o1.y *= m1v.y;
            }
            *(float2*)&Y[off0] = o0;
            *(float2*)&Y[off1] = o1;
        }
    }
}

// ---------------- FFT-domain circular conv per (b,c) ----------------
#define FFT_SMEM_FLOATS (128 + 4096 + 3 * 2 * 4096)
#define FFT_SMEM_BYTES  (FFT_SMEM_FLOATS * 4)   // 115200

__global__ __launch_bounds__(512) void fft_attn_kernel(
    float* __restrict__ Aq /* in: q, out: A */, const float* __restrict__ Kk)
{
    extern __shared__ float sm[];
    float2* tw  = (float2*)sm;
    float*  inb = sm + 128;
    float2* T   = (float2*)(sm + 128 + 4096);
    float2* Fq  = T + 4096;
    float2* Fk  = Fq + 4096;

    int tid = threadIdx.x;
    size_t base = (size_t)blockIdx.x * HW_;
    int l  = tid & 63;
    int jb = (tid >> 6) * 8;

    if (tid < 64) {
        float ang = -2.f * PI_F * (float)tid / 64.f;
        tw[tid] = make_float2(cosf(ang), sinf(ang));
    }
    __syncthreads();

    for (int field = 0; field < 2; field++) {
        const float* src = (field == 0) ? (Aq + base) : (Kk + base);
        float2* dst = (field == 0) ? Fq : Fk;

        for (int i = tid; i < 4096; i += 512) inb[i] = src[i];
        __syncthreads();

        {
            float ar[8], ai[8];
#pragma unroll
            for (int jj = 0; jj < 8; jj++) { ar[jj] = 0.f; ai[jj] = 0.f; }
            for (int m = 0; m < 64; m++) {
                float xv = inb[m * 64 + l];
#pragma unroll
                for (int jj = 0; jj < 8; jj++) {
                    float2 c = tw[((jb + jj) * m) & 63];
                    ar[jj] += c.x * xv;
                    ai[jj] += c.y * xv;
                }
            }
#pragma unroll
            for (int jj = 0; jj < 8; jj++)
                T[(jb + jj) * 64 + l] = make_float2(ar[jj], ai[jj]);
        }
        __syncthreads();

        {
            float2 wl = tw[l];
            float cr = 1.f, ci = 0.f;
            float ar[8], ai[8];
#pragma unroll
            for (int jj = 0; jj < 8; jj++) { ar[jj] = 0.f; ai[jj] = 0.f; }
            for (int m = 0; m < 64; m++) {
#pragma unroll
                for (int jj = 0; jj < 8; jj++) {
                    float2 t = T[(jb + jj) * 64 + m];
                    ar[jj] += t.x * cr - t.y * ci;
                    ai[jj] += t.x * ci + t.y * cr;
                }
                float nr = cr * wl.x - ci * wl.y;
                ci = cr * wl.y + ci * wl.x;
                cr = nr;
            }
#pragma unroll
            for (int jj = 0; jj < 8; jj++)
                dst[(jb + jj) * 64 + l] = make_float2(ar[jj], ai[jj]);
        }
        __syncthreads();
    }

    for (int i = tid; i < 4096; i += 512) {
        float2 a = Fq[i], bq = Fk[i];
        Fq[i] = make_float2(a.x * bq.x - a.y * bq.y, a.x * bq.y + a.y * bq.x);
    }
    __syncthreads();

    {
        float ar[8], ai[8];
#pragma unroll
        for (int jj = 0; jj < 8; jj++) { ar[jj] = 0.f; ai[jj] = 0.f; }
        for (int m = 0; m < 64; m++) {
            float2 p = Fq[m * 64 + l];
#pragma unroll
            for (int jj = 0; jj < 8; jj++) {
                float2 c = tw[((jb + jj) * m) & 63];
                ar[jj] += c.x * p.x + c.y * p.y;
                ai[jj] += c.x * p.y - c.y * p.x;
            }
        }
#pragma unroll
        for (int jj = 0; jj < 8; jj++)
            T[(jb + jj) * 64 + l] = make_float2(ar[jj], ai[jj]);
    }
    __syncthreads();

    {
        float2 wl = tw[l];
        float cr = 1.f, ci = 0.f;
        float ar[8];
#pragma unroll
        for (int jj = 0; jj < 8; jj++) ar[jj] = 0.f;
        for (int m = 0; m < 64; m++) {
#pragma unroll
            for (int jj = 0; jj < 8; jj++) {
                float2 t = T[(jb + jj) * 64 + m];
                ar[jj] += t.x * cr + t.y * ci;
            }
            float nr = cr * wl.x - ci * wl.y;
            ci = cr * wl.y + ci * wl.x;
            cr = nr;
        }
#pragma unroll
        for (int jj = 0; jj < 8; jj++)
            Aq[base + (size_t)(jb + jj) * 64 + l] = ar[jj] * (1.f / 4096.f);
    }
}

// ---------------- top-k(512) threshold + masked softmax + multiply by v ----------------
__device__ __forceinline__ unsigned f2ord(float f) {
    unsigned b = __float_as_uint(f);
    return (b & 0x80000000u) ? ~b : (b | 0x80000000u);
}
__device__ __forceinline__ float ord2f(unsigned u) {
    unsigned b = (u & 0x80000000u) ? (u ^ 0x80000000u) : ~u;
    return __uint_as_float(b);
}

__global__ __launch_bounds__(256) void topk_softmax_kernel(
    float* __restrict__ A, const float* __restrict__ V)
{
    __shared__ unsigned ua[4096];
    __shared__ unsigned hist[256];
    __shared__ float redf[256];
    __shared__ unsigned s_prefix;
    __shared__ int s_kk;
    __shared__ float s_maxf;

    int tid = threadIdx.x;
    size_t base = (size_t)blockIdx.x * HW_;

    unsigned mymax = 0u;
    for (int i = tid; i < 4096; i += 256) {
        unsigned u = f2ord(A[base + i]);
        ua[i] = u;
        mymax = max(mymax, u);
    }
    hist[tid] = mymax;
    __syncthreads();
    for (int o = 128; o > 0; o >>= 1) {
        if (tid < o) hist[tid] = max(hist[tid], hist[tid + o]);
        __syncthreads();
    }
    if (tid == 0) {
        s_maxf = ord2f(hist[0]);
        s_kk = KTOP_;
        s_prefix = 0u;
    }
    __syncthreads();

    for (int level = 3; level >= 0; level--) {
        hist[tid] = 0u;
        __syncthreads();
        int shift = level * 8;
        unsigned maskhi = (level == 3) ? 0u : (0xFFFFFFFFu << (shift + 8));
        unsigned prefix = s_prefix;
        for (int i = tid; i < 4096; i += 256) {
            unsigned u = ua[i];
            if ((u & maskhi) == prefix)
                atomicAdd(&hist[(u >> shift) & 255], 1u);
        }
        __syncthreads();
        if (tid == 0) {
            int kk = s_kk;
            unsigned cum = 0;
            int d = 255;
            for (; d >= 0; d--) {
                unsigned c = hist[d];
                if (cum + c >= (unsigned)kk) break;
                cum += c;
            }
            if (d < 0) d = 0;
            s_kk = kk - (int)cum;
            s_prefix = prefix | ((unsigned)d << shift);
        }
        __syncthreads();
    }

    unsigned thr = s_prefix;
    float maxf = s_maxf;

    float ssum = 0.f;
    for (int i = tid; i < 4096; i += 256) {
        unsigned u = ua[i];
        if (u >= thr) ssum += expf(ord2f(u) - maxf);
    }
    redf[tid] = ssum;
    __syncthreads();
    for (int o = 128; o > 0; o >>= 1) {
        if (tid < o) redf[tid] += redf[tid + o];
        __syncthreads();
    }
    float inv = 1.f / redf[0];

    for (int i = tid; i < 4096; i += 256) {
        unsigned u = ua[i];
        float o = 0.f;
        if (u >= thr) o = V[base + i] * expf(ord2f(u) - maxf) * inv;
        A[base + i] = o;
    }
}

// ---------------- launch ----------------
extern "C" void kernel_launch(void* const* d_in, const int* in_sizes, int n_in,
                              void* d_out, int out_size)
{
    const float* x     = (const float*)d_in[0];
    const float* gamma = (const float*)d_in[1];
    const float* beta  = (const float*)d_in[2];
    const float* wq    = (const float*)d_in[3];
    const float* bq    = (const float*)d_in[4];
    const float* wk    = (const float*)d_in[5];
    const float* bk    = (const float*)d_in[6];
    const float* wv    = (const float*)d_in[7];
    const float* bv    = (const float*)d_in[8];
    const float* wf    = (const float*)d_in[9];
    const float* bf    = (const float*)d_in[10];
    float* out = (float*)d_out;

    void *pxn, *pq, *pk, *pv;
    cudaGetSymbolAddress(&pxn, g_xn);
    cudaGetSymbolAddress(&pq,  g_q);
    cudaGetSymbolAddress(&pk,  g_k);
    cudaGetSymbolAddress(&pv,  g_v);

    cudaFuncSetAttribute(fft_attn_kernel,
                         cudaFuncAttributeMaxDynamicSharedMemorySize, FFT_SMEM_BYTES);

    // 1. GroupNorm
    groupnorm_kernel<<<B_ * NG_, 256>>>(x, gamma, beta);

    // 2-4. q / v (1x1) and k (3x3) projections (tensor-core split-tf32)
    dim3 gg(HW_ / 128, C_ / 128, B_);
    gemm_tc_kernel<C_,     false, false><<<gg, 256>>>(wq, (const float*)pxn, bq, (float*)pq);
    gemm_tc_kernel<C_,     false, false><<<gg, 256>>>(wv, (const float*)pxn, bv, (float*)pv);
    gemm_tc_kernel<C_ * 9, true,  false><<<gg, 256>>>(wk, (const float*)pxn, bk, (float*)pk);

    // 5. FFT circular conv: A (into g_q)
    fft_attn_kernel<<<B_ * C_, 512, FFT_SMEM_BYTES>>>((float*)pq, (const float*)pk);

    // 6. top-k + softmax + v-multiply: F4 (into g_q)
    topk_softmax_kernel<<<B_ * C_, 256>>>((float*)pq, (const float*)pv);

    // 7. final 1x1 conv with xn-multiply epilogue
    gemm_tc_kernel<C_,     false, true ><<<gg, 256>>>(wf, (const float*)pq, bf, out);
}

// round 5
// speedup vs baseline: 1.6621x; 1.0306x over previous
#include <cuda_runtime.h>
#include <math.h>
#include <stdint.h>

#define B_    8
#define C_    384
#define HW_   4096
#define HWDIM 64
#define NG_   32
#define CPG_  12
#define KTOP_ 512
#define PI_F  3.14159265358979323846f

// ---------------- scratch (device globals; no allocation) ----------------
__device__ float g_xn [(size_t)B_ * C_ * HW_];
__device__ float g_xnh[(size_t)B_ * C_ * HW_];
__device__ float g_xnl[(size_t)B_ * C_ * HW_];
__device__ float g_q  [(size_t)B_ * C_ * HW_];   // q -> A (FFT out)
__device__ float g_k  [(size_t)B_ * C_ * HW_];   // k -> F4_hi (topk out)
__device__ float g_v  [(size_t)B_ * C_ * HW_];   // v -> F4_lo (topk out)
// transposed split weight planes [k][m]
__device__ float g_wkh[(size_t)384 * 3456];
__device__ float g_wkl[(size_t)384 * 3456];
__device__ float g_wqh[384 * 384], g_wql[384 * 384];
__device__ float g_wvh[384 * 384], g_wvl[384 * 384];
__device__ float g_wfh[384 * 384], g_wfl[384 * 384];

// ---------------- helpers ----------------
__device__ __forceinline__ float tf32_round(float x) {
    unsigned r;
    asm("cvt.rna.tf32.f32 %0, %1;" : "=r"(r) : "f"(x));
    return __uint_as_float(r);
}

__device__ __forceinline__ void mma_tf32(
    float* c, unsigned a0, unsigned a1, unsigned a2, unsigned a3,
    unsigned b0, unsigned b1)
{
    asm volatile(
        "mma.sync.aligned.m16n8k8.row.col.f32.tf32.tf32.f32 "
        "{%0,%1,%2,%3}, {%4,%5,%6,%7}, {%8,%9}, {%0,%1,%2,%3};"
        : "+f"(c[0]), "+f"(c[1]), "+f"(c[2]), "+f"(c[3])
        : "r"(a0), "r"(a1), "r"(a2), "r"(a3), "r"(b0), "r"(b1));
}

__device__ __forceinline__ void cp16(void* dst, const float* src) {
    unsigned d = (unsigned)__cvta_generic_to_shared(dst);
    asm volatile("cp.async.cg.shared.global [%0], [%1], 16;" :: "r"(d), "l"(src));
}
#define CP_COMMIT() asm volatile("cp.async.commit_group;" ::: "memory")
#define CP_WAIT0()  asm volatile("cp.async.wait_group 0;" ::: "memory")

// ---------------- weight split+transpose prep: W[m][k] -> hi/lo [k][m=384] ----------------
__global__ void wsplit_kernel(const float* __restrict__ w,
                              float* __restrict__ ht, float* __restrict__ lt, int K)
{
    __shared__ float tile[32][33];
    int k0 = blockIdx.x * 32, m0 = blockIdx.y * 32;
    int tx = threadIdx.x, ty = threadIdx.y;
#pragma unroll
    for (int j = 0; j < 32; j += 8)
        tile[ty + j][tx] = w[(size_t)(m0 + ty + j) * K + k0 + tx];
    __syncthreads();
#pragma unroll
    for (int j = 0; j < 32; j += 8) {
        float v = tile[tx][ty + j];
        float h = tf32_round(v);
        size_t o = (size_t)(k0 + ty + j) * 384 + m0 + tx;
        ht[o] = h;
        lt[o] = tf32_round(v - h);
    }
}

// ---------------- GroupNorm (emits xn + hi/lo planes) ----------------
__global__ __launch_bounds__(256) void groupnorm_kernel(
    const float* __restrict__ x, const float* __restrict__ gamma,
    const float* __restrict__ beta)
{
    int b = blockIdx.x / NG_;
    int g = blockIdx.x % NG_;
    size_t base = ((size_t)b * C_ + (size_t)g * CPG_) * HW_;
    const int n = CPG_ * HW_;
    int tid = threadIdx.x;

    float s = 0.f, ss = 0.f;
    for (int i = tid; i < n; i += 256) {
        float v = x[base + i];
        s += v; ss += v * v;
    }
    __shared__ float rs[256], rss[256];
    rs[tid] = s; rss[tid] = ss;
    __syncthreads();
    for (int o = 128; o > 0; o >>= 1) {
        if (tid < o) { rs[tid] += rs[tid + o]; rss[tid] += rss[tid + o]; }
        __syncthreads();
    }
    float mean = rs[0] / (float)n;
    float var  = rss[0] / (float)n - mean * mean;
    float inv  = rsqrtf(var + 1e-5f);

    for (int i = tid; i < n; i += 256) {
        int c = g * CPG_ + i / HW_;
        float v = (x[base + i] - mean) * inv;
        v = v * gamma[c] + beta[c];
        g_xn[base + i] = v;
        float h = tf32_round(v);
        g_xnh[base + i] = h;
        g_xnl[base + i] = tf32_round(v - h);
    }
}

// ---------------- tensor-core GEMM, precomputed split planes, cp.async, BK=16 ----------------
// Y[b,m,n] = sum_k W[m,k]*B(k,n) + bias[m]
//   CONV3=false: B planes bhp/blp are [b][k][n] hi/lo            (KTOT=384)
//   CONV3=true : bhp = raw xn, implicit 3x3 gather, split on STS (KTOT=3456)
//   MULXN: multiply output by g_xn
#define SA_ 136
#define PF_ (16 * SA_)                 // floats per plane buffer (2176)
#define GEMM_SMEM_B (8 * PF_ * 4)      // 69632 bytes

template <int KTOT, bool CONV3, bool MULXN>
__global__ __launch_bounds__(256, 2) void gemm_mma_kernel(
    const float* __restrict__ whT, const float* __restrict__ wlT,
    const float* __restrict__ bhp, const float* __restrict__ blp,
    const float* __restrict__ bias, float* __restrict__ Y)
{
    extern __shared__ float smf[];
    float* AHb = smf;
    float* ALb = smf + 2 * PF_;
    float* BHb = smf + 4 * PF_;
    float* BLb = smf + 6 * PF_;

    const int b  = blockIdx.z;
    const int n0 = blockIdx.x * 128;
    const int m0 = blockIdx.y * 128;
    const float* Bh = bhp + (size_t)b * C_ * HW_;
    const float* Bl = blp + (size_t)b * C_ * HW_;

    const int tid  = threadIdx.x;
    const int lane = tid & 31;
    const int wid  = tid >> 5;
    const int wm   = wid & 1;
    const int wn   = wid >> 1;
    const int g    = lane >> 2;
    const int t    = lane & 3;
    const int sk   = tid >> 4;        // 0..15
    const int sf   = (tid & 15) * 8;  // 0..120

    float acc[4][4][4];
#pragma unroll
    for (int mi = 0; mi < 4; mi++)
#pragma unroll
        for (int ni = 0; ni < 4; ni++)
#pragma unroll
            for (int r = 0; r < 4; r++) acc[mi][ni][r] = 0.f;

    const int NIT = KTOT / 16;
    float bv[8];

    // ---- prologue: tile 0 -> buffer 0 ----
    {
        const float* wh = whT + (size_t)sk * 384 + m0 + sf;
        const float* wl = wlT + (size_t)sk * 384 + m0 + sf;
        cp16(&AHb[sk * SA_ + sf],     wh);
        cp16(&AHb[sk * SA_ + sf + 4], wh + 4);
        cp16(&ALb[sk * SA_ + sf],     wl);
        cp16(&ALb[sk * SA_ + sf + 4], wl + 4);
        if (!CONV3) {
            const float* xh = Bh + (size_t)sk * HW_ + n0 + sf;
            const float* xl = Bl + (size_t)sk * HW_ + n0 + sf;
            cp16(&BHb[sk * SA_ + sf],     xh);
            cp16(&BHb[sk * SA_ + sf + 4], xh + 4);
            cp16(&BLb[sk * SA_ + sf],     xl);
            cp16(&BLb[sk * SA_ + sf + 4], xl + 4);
        }
        CP_COMMIT();
        if (CONV3) {
            const int kk = sk;
            const int ci = kk / 9, rs = kk - ci * 9;
            const int dy = rs / 3 - 1, dx = rs % 3 - 1;
#pragma unroll
            for (int j = 0; j < 8; j++) {
                const int n = n0 + sf + j;
                const int h = (n >> 6) + dy, w = (n & 63) + dx;
                bv[j] = (h >= 0 && h < HWDIM && w >= 0 && w < HWDIM)
                            ? Bh[(size_t)ci * HW_ + h * HWDIM + w] : 0.f;
            }
#pragma unroll
            for (int j = 0; j < 8; j++) {
                float h = tf32_round(bv[j]);
                BHb[sk * SA_ + sf + j] = h;
                BLb[sk * SA_ + sf + j] = tf32_round(bv[j] - h);
            }
        }
    }

    for (int it = 0; it < NIT; it++) {
        const int p = it & 1;
        const int q = 1 - p;
        float* AH  = AHb + p * PF_;
        float* AL  = ALb + p * PF_;
        float* BHs = BHb + p * PF_;
        float* BLs = BLb + p * PF_;

        CP_WAIT0();
        __syncthreads();

        const bool next = (it + 1 < NIT);
        if (next) {
            const int k0 = (it + 1) * 16;
            const float* wh = whT + (size_t)(k0 + sk) * 384 + m0 + sf;
            const float* wl = wlT + (size_t)(k0 + sk) * 384 + m0 + sf;
            cp16(&AHb[q * PF_ + sk * SA_ + sf],     wh);
            cp16(&AHb[q * PF_ + sk * SA_ + sf + 4], wh + 4);
            cp16(&ALb[q * PF_ + sk * SA_ + sf],     wl);
            cp16(&ALb[q * PF_ + sk * SA_ + sf + 4], wl + 4);
            if (!CONV3) {
                const float* xh = Bh + (size_t)(k0 + sk) * HW_ + n0 + sf;
                const float* xl = Bl + (size_t)(k0 + sk) * HW_ + n0 + sf;
                cp16(&BHb[q * PF_ + sk * SA_ + sf],     xh);
                cp16(&BHb[q * PF_ + sk * SA_ + sf + 4], xh + 4);
                cp16(&BLb[q * PF_ + sk * SA_ + sf],     xl);
                cp16(&BLb[q * PF_ + sk * SA_ + sf + 4], xl + 4);
            }
            CP_COMMIT();
            if (CONV3) {
                const int kk = k0 + sk;
                const int ci = kk / 9, rs = kk - ci * 9;
                const int dy = rs / 3 - 1, dx = rs % 3 - 1;
#pragma unroll
                for (int j = 0; j < 8; j++) {
                    const int n = n0 + sf + j;
                    const int h = (n >> 6) + dy, w = (n & 63) + dx;
                    bv[j] = (h >= 0 && h < HWDIM && w >= 0 && w < HWDIM)
                                ? Bh[(size_t)ci * HW_ + h * HWDIM + w] : 0.f;
                }
            }
        }

        // ---- compute buffer p: two k8 substeps ----
#pragma unroll
        for (int ks = 0; ks < 2; ks++) {
            const int r0 = ks * 8 + t, r1 = r0 + 4;
            unsigned ah[4][4], al[4][4], bh[4][2], bl[4][2];
#pragma unroll
            for (int mi = 0; mi < 4; mi++) {
                const int mb = wm * 64 + mi * 16 + g;
                ah[mi][0] = __float_as_uint(AH[r0 * SA_ + mb]);
                ah[mi][1] = __float_as_uint(AH[r0 * SA_ + mb + 8]);
                ah[mi][2] = __float_as_uint(AH[r1 * SA_ + mb]);
                ah[mi][3] = __float_as_uint(AH[r1 * SA_ + mb + 8]);
                al[mi][0] = __float_as_uint(AL[r0 * SA_ + mb]);
                al[mi][1] = __float_as_uint(AL[r0 * SA_ + mb + 8]);
                al[mi][2] = __float_as_uint(AL[r1 * SA_ + mb]);
                al[mi][3] = __float_as_uint(AL[r1 * SA_ + mb + 8]);
            }
#pragma unroll
            for (int ni = 0; ni < 4; ni++) {
                const int nb = wn * 32 + ni * 8 + g;
                bh[ni][0] = __float_as_uint(BHs[r0 * SA_ + nb]);
                bh[ni][1] = __float_as_uint(BHs[r1 * SA_ + nb]);
                bl[ni][0] = __float_as_uint(BLs[r0 * SA_ + nb]);
                bl[ni][1] = __float_as_uint(BLs[r1 * SA_ + nb]);
            }
            // term-outer ordering: consecutive MMAs hit distinct accumulators
#pragma unroll
            for (int mi = 0; mi < 4; mi++)
#pragma unroll
                for (int ni = 0; ni < 4; ni++)
                    mma_tf32(acc[mi][ni], ah[mi][0], ah[mi][1], ah[mi][2], ah[mi][3],
                             bh[ni][0], bh[ni][1]);
#pragma unroll
            for (int mi = 0; mi < 4; mi++)
#pragma unroll
                for (int ni = 0; ni < 4; ni++)
                    mma_tf32(acc[mi][ni], ah[mi][0], ah[mi][1], ah[mi][2], ah[mi][3],
                             bl[ni][0], bl[ni][1]);
#pragma unroll
            for (int mi = 0; mi < 4; mi++)
#pragma unroll
                for (int ni = 0; ni < 4; ni++)
                    mma_tf32(acc[mi][ni], al[mi][0], al[mi][1], al[mi][2], al[mi][3],
                             bh[ni][0], bh[ni][1]);
        }

        if (next && CONV3) {
#pragma unroll
            for (int j = 0; j < 8; j++) {
                float h = tf32_round(bv[j]);
                BHb[q * PF_ + sk * SA_ + sf + j] = h;
                BLb[q * PF_ + sk * SA_ + sf + j] = tf32_round(bv[j] - h);
            }
        }
        __syncthreads();
    }

    // ---- epilogue ----
    const size_t ybase = (size_t)b * C_ * HW_;
#pragma unroll
    for (int mi = 0; mi < 4; mi++) {
        const int r0 = m0 + wm * 64 + mi * 16 + g;
        const int r1 = r0 + 8;
        const float bi0 = bias[r0];
        const float bi1 = bias[r1];
#pragma unroll
        for (int ni = 0; ni < 4; ni++) {
            const int col = n0 + wn * 32 + ni * 8 + 2 * t;
            float2 o0 = make_float2(acc[mi][ni][0] + bi0, acc[mi][ni][1] + bi0);
            float2 o1 = make_float2(acc[mi][ni][2] + bi1, acc[mi][ni][3] + bi1);
            size_t off0 = ybase + (size_t)r0 * HW_ + col;
            size_t off1 = ybase + (size_t)r1 * HW_ + col;
            if (MULXN) {
                float2 m0v = *(const float2*)&g_xn[off0];
                float2 m1v = *(const float2*)&g_xn[off1];
                o0.x *= m0v.x; o0.y *= m0v.y;
                o1.x *= m1v.x; o1.y *= m1v.y;
            }
            *(float2*)&Y[off0] = o0;
            *(float2*)&Y[off1] = o1;
        }
    }
}

// ---------------- FFT-domain circular conv per (b,c) ----------------
#define FFT_SMEM_FLOATS (128 + 4096 + 3 * 2 * 4096)
#define FFT_SMEM_BYTES  (FFT_SMEM_FLOATS * 4)   // 115200

__global__ __launch_bounds__(512) void fft_attn_kernel(
    float* __restrict__ Aq /* in: q, out: A */, const float* __restrict__ Kk)
{
    extern __shared__ float smf[];
    float2* tw  = (float2*)smf;
    float*  inb = smf + 128;
    float2* T   = (float2*)(smf + 128 + 4096);
    float2* Fq  = T + 4096;
    float2* Fk  = Fq + 4096;

    int tid = threadIdx.x;
    size_t base = (size_t)blockIdx.x * HW_;
    int l  = tid & 63;
    int jb = (tid >> 6) * 8;

    if (tid < 64) {
        float ang = -2.f * PI_F * (float)tid / 64.f;
        tw[tid] = make_float2(cosf(ang), sinf(ang));
    }
    __syncthreads();

    for (int field = 0; field < 2; field++) {
        const float* src = (field == 0) ? (Aq + base) : (Kk + base);
        float2* dst = (field == 0) ? Fq : Fk;

        for (int i = tid; i < 4096; i += 512) inb[i] = src[i];
        __syncthreads();

        {
            float ar[8], ai[8];
#pragma unroll
            for (int jj = 0; jj < 8; jj++) { ar[jj] = 0.f; ai[jj] = 0.f; }
            for (int m = 0; m < 64; m++) {
                float xv = inb[m * 64 + l];
#pragma unroll
                for (int jj = 0; jj < 8; jj++) {
                    float2 c = tw[((jb + jj) * m) & 63];
                    ar[jj] += c.x * xv;
                    ai[jj] += c.y * xv;
                }
            }
#pragma unroll
            for (int jj = 0; jj < 8; jj++)
                T[(jb + jj) * 64 + l] = make_float2(ar[jj], ai[jj]);
        }
        __syncthreads();

        {
            float2 wl = tw[l];
            float cr = 1.f, ci = 0.f;
            float ar[8], ai[8];
#pragma unroll
            for (int jj = 0; jj < 8; jj++) { ar[jj] = 0.f; ai[jj] = 0.f; }
            for (int m = 0; m < 64; m++) {
#pragma unroll
                for (int jj = 0; jj < 8; jj++) {
                    float2 t = T[(jb + jj) * 64 + m];
                    ar[jj] += t.x * cr - t.y * ci;
                    ai[jj] += t.x * ci + t.y * cr;
                }
                float nr = cr * wl.x - ci * wl.y;
                ci = cr * wl.y + ci * wl.x;
                cr = nr;
            }
#pragma unroll
            for (int jj = 0; jj < 8; jj++)
                dst[(jb + jj) * 64 + l] = make_float2(ar[jj], ai[jj]);
        }
        __syncthreads();
    }

    for (int i = tid; i < 4096; i += 512) {
        float2 a = Fq[i], bq = Fk[i];
        Fq[i] = make_float2(a.x * bq.x - a.y * bq.y, a.x * bq.y + a.y * bq.x);
    }
    __syncthreads();

    {
        float ar[8], ai[8];
#pragma unroll
        for (int jj = 0; jj < 8; jj++) { ar[jj] = 0.f; ai[jj] = 0.f; }
        for (int m = 0; m < 64; m++) {
            float2 p = Fq[m * 64 + l];
#pragma unroll
            for (int jj = 0; jj < 8; jj++) {
                float2 c = tw[((jb + jj) * m) & 63];
                ar[jj] += c.x * p.x + c.y * p.y;
                ai[jj] += c.x * p.y - c.y * p.x;
            }
        }
#pragma unroll
        for (int jj = 0; jj < 8; jj++)
            T[(jb + jj) * 64 + l] = make_float2(ar[jj], ai[jj]);
    }
    __syncthreads();

    {
        float2 wl = tw[l];
        float cr = 1.f, ci = 0.f;
        float ar[8];
#pragma unroll
        for (int jj = 0; jj < 8; jj++) ar[jj] = 0.f;
        for (int m = 0; m < 64; m++) {
#pragma unroll
            for (int jj = 0; jj < 8; jj++) {
                float2 t = T[(jb + jj) * 64 + m];
                ar[jj] += t.x * cr + t.y * ci;
            }
            float nr = cr * wl.x - ci * wl.y;
            ci = cr * wl.y + ci * wl.x;
            cr = nr;
        }
#pragma unroll
        for (int jj = 0; jj < 8; jj++)
            Aq[base + (size_t)(jb + jj) * 64 + l] = ar[jj] * (1.f / 4096.f);
    }
}

// ---------------- top-k(512) + masked softmax + v-mul, emits F4 hi/lo planes ----------------
__device__ __forceinline__ unsigned f2ord(float f) {
    unsigned b = __float_as_uint(f);
    return (b & 0x80000000u) ? ~b : (b | 0x80000000u);
}
__device__ __forceinline__ float ord2f(unsigned u) {
    unsigned b = (u & 0x80000000u) ? (u ^ 0x80000000u) : ~u;
    return __uint_as_float(b);
}

__global__ __launch_bounds__(256) void topk_softmax_kernel(
    const float* __restrict__ A, const float* __restrict__ V,
    float* __restrict__ Hout, float* __restrict__ Lout)
{
    __shared__ unsigned ua[4096];
    __shared__ unsigned hist[256];
    __shared__ float redf[256];
    __shared__ unsigned s_prefix;
    __shared__ int s_kk;
    __shared__ float s_maxf;

    int tid = threadIdx.x;
    size_t base = (size_t)blockIdx.x * HW_;

    unsigned mymax = 0u;
    for (int i = tid; i < 4096; i += 256) {
        unsigned u = f2ord(A[base + i]);
        ua[i] = u;
        mymax = max(mymax, u);
    }
    hist[tid] = mymax;
    __syncthreads();
    for (int o = 128; o > 0; o >>= 1) {
        if (tid < o) hist[tid] = max(hist[tid], hist[tid + o]);
        __syncthreads();
    }
    if (tid == 0) {
        s_maxf = ord2f(hist[0]);
        s_kk = KTOP_;
        s_prefix = 0u;
    }
    __syncthreads();

    for (int level = 3; level >= 0; level--) {
        hist[tid] = 0u;
        __syncthreads();
        int shift = level * 8;
        unsigned maskhi = (level == 3) ? 0u : (0xFFFFFFFFu << (shift + 8));
        unsigned prefix = s_prefix;
        for (int i = tid; i < 4096; i += 256) {
            unsigned u = ua[i];
            if ((u & maskhi) == prefix)
                atomicAdd(&hist[(u >> shift) & 255], 1u);
        }
        __syncthreads();
        if (tid == 0) {
            int kk = s_kk;
            unsigned cum = 0;
            int d = 255;
            for (; d >= 0; d--) {
                unsigned c = hist[d];
                if (cum + c >= (unsigned)kk) break;
                cum += c;
            }
            if (d < 0) d = 0;
            s_kk = kk - (int)cum;
            s_prefix = prefix | ((unsigned)d << shift);
        }
        __syncthreads();
    }

    unsigned thr = s_prefix;
    float maxf = s_maxf;

    float ssum = 0.f;
    for (int i = tid; i < 4096; i += 256) {
        unsigned u = ua[i];
        if (u >= thr) ssum += expf(ord2f(u) - maxf);
    }
    redf[tid] = ssum;
    __syncthreads();
    for (int o = 128; o > 0; o >>= 1) {
        if (tid < o) redf[tid] += redf[tid + o];
        __syncthreads();
    }
    float inv = 1.f / redf[0];

    for (int i = tid; i < 4096; i += 256) {
        unsigned u = ua[i];
        float o = 0.f;
        if (u >= thr) o = V[base + i] * expf(ord2f(u) - maxf) * inv;
        float h = tf32_round(o);
        Hout[base + i] = h;
        Lout[base + i] = tf32_round(o - h);
    }
}

// ---------------- launch ----------------
extern "C" void kernel_launch(void* const* d_in, const int* in_sizes, int n_in,
                              void* d_out, int out_size)
{
    const float* x     = (const float*)d_in[0];
    const float* gamma = (const float*)d_in[1];
    const float* beta  = (const float*)d_in[2];
    const float* wq    = (const float*)d_in[3];
    const float* bq    = (const float*)d_in[4];
    const float* wk    = (const float*)d_in[5];
    const float* bk    = (const float*)d_in[6];
    const float* wv    = (const float*)d_in[7];
    const float* bv    = (const float*)d_in[8];
    const float* wf    = (const float*)d_in[9];
    const float* bf    = (const float*)d_in[10];
    float* out = (float*)d_out;

    void *pxn, *pxnh, *pxnl, *pq, *pk, *pv;
    void *pwkh, *pwkl, *pwqh, *pwql, *pwvh, *pwvl, *pwfh, *pwfl;
    cudaGetSymbolAddress(&pxn,  g_xn);
    cudaGetSymbolAddress(&pxnh, g_xnh);
    cudaGetSymbolAddress(&pxnl, g_xnl);
    cudaGetSymbolAddress(&pq,   g_q);
    cudaGetSymbolAddress(&pk,   g_k);
    cudaGetSymbolAddress(&pv,   g_v);
    cudaGetSymbolAddress(&pwkh, g_wkh);
    cudaGetSymbolAddress(&pwkl, g_wkl);
    cudaGetSymbolAddress(&pwqh, g_wqh);
    cudaGetSymbolAddress(&pwql, g_wql);
    cudaGetSymbolAddress(&pwvh, g_wvh);
    cudaGetSymbolAddress(&pwvl, g_wvl);
    cudaGetSymbolAddress(&pwfh, g_wfh);
    cudaGetSymbolAddress(&pwfl, g_wfl);

    cudaFuncSetAttribute(fft_attn_kernel,
                         cudaFuncAttributeMaxDynamicSharedMemorySize, FFT_SMEM_BYTES);
    cudaFuncSetAttribute((const void*)gemm_mma_kernel<C_, false, false>,
                         cudaFuncAttributeMaxDynamicSharedMemorySize, GEMM_SMEM_B);
    cudaFuncSetAttribute((const void*)gemm_mma_kernel<C_, false, true>,
                         cudaFuncAttributeMaxDynamicSharedMemorySize, GEMM_SMEM_B);
    cudaFuncSetAttribute((const void*)gemm_mma_kernel<C_ * 9, true, false>,
                         cudaFuncAttributeMaxDynamicSharedMemorySize, GEMM_SMEM_B);

    // 0. weight split+transpose prep
    dim3 wb(32, 8);
    wsplit_kernel<<<dim3(12, 12),  wb>>>(wq, (float*)pwqh, (float*)pwql, 384);
    wsplit_kernel<<<dim3(12, 12),  wb>>>(wv, (float*)pwvh, (float*)pwvl, 384);
    wsplit_kernel<<<dim3(12, 12),  wb>>>(wf, (float*)pwfh, (float*)pwfl, 384);
    wsplit_kernel<<<dim3(108, 12), wb>>>(wk, (float*)pwkh, (float*)pwkl, 3456);

    // 1. GroupNorm (+ hi/lo planes)
    groupnorm_kernel<<<B_ * NG_, 256>>>(x, gamma, beta);

    // 2-4. q / v (1x1) and k (3x3) projections
    dim3 gg(HW_ / 128, C_ / 128, B_);
    gemm_mma_kernel<C_, false, false><<<gg, 256, GEMM_SMEM_B>>>(
        (const float*)pwqh, (const float*)pwql,
        (const float*)pxnh, (const float*)pxnl, bq, (float*)pq);
    gemm_mma_kernel<C_, false, false><<<gg, 256, GEMM_SMEM_B>>>(
        (const float*)pwvh, (const float*)pwvl,
        (const float*)pxnh, (const float*)pxnl, bv, (float*)pv);
    gemm_mma_kernel<C_ * 9, true, false><<<gg, 256, GEMM_SMEM_B>>>(
        (const float*)pwkh, (const float*)pwkl,
        (const float*)pxn, (const float*)pxn, bk, (float*)pk);

    // 5. FFT circular conv: A (into g_q)
    fft_attn_kernel<<<B_ * C_, 512, FFT_SMEM_BYTES>>>((float*)pq, (const float*)pk);

    // 6. top-k + softmax + v-mul -> F4 hi/lo planes (into g_k / g_v)
    topk_softmax_kernel<<<B_ * C_, 256>>>((const float*)pq, (const float*)pv,
                                          (float*)pk, (float*)pv);

    // 7. final 1x1 conv with xn-multiply epilogue
    gemm_mma_kernel<C_, false, true><<<gg, 256, GEMM_SMEM_B>>>(
        (const float*)pwfh, (const float*)pwfl,
        (const float*)pk, (const float*)pv, bf, out);
}

// round 6
// speedup vs baseline: 2.4335x; 1.4642x over previous
#include <cuda_runtime.h>
#include <cuda_bf16.h>
#include <math.h>
#include <stdint.h>

#define B_    8
#define C_    384
#define HW_   4096
#define HWDIM 64
#define NG_   32
#define CPG_  12
#define KTOP_ 512
#define PI_F  3.14159265358979323846f

// ---------------- scratch (device globals; no allocation) ----------------
__device__ float g_xn [(size_t)B_ * C_ * HW_];
__device__ float g_q  [(size_t)B_ * C_ * HW_];   // q -> A (FFT out)
__device__ float g_k  [(size_t)B_ * C_ * HW_];   // 3x3-conv k output
__device__ float g_v  [(size_t)B_ * C_ * HW_];   // v output
__device__ __nv_bfloat16 g_xnh[(size_t)B_ * C_ * HW_];
__device__ __nv_bfloat16 g_xnl[(size_t)B_ * C_ * HW_];
__device__ __nv_bfloat16 g_f4h[(size_t)B_ * C_ * HW_];
__device__ __nv_bfloat16 g_f4l[(size_t)B_ * C_ * HW_];
// tiled split weight planes: [K/16][384][16] bf16
__device__ __nv_bfloat16 g_wkh[(size_t)384 * 3456];
__device__ __nv_bfloat16 g_wkl[(size_t)384 * 3456];
__device__ __nv_bfloat16 g_wqh[384 * 384], g_wql[384 * 384];
__device__ __nv_bfloat16 g_wvh[384 * 384], g_wvl[384 * 384];
__device__ __nv_bfloat16 g_wfh[384 * 384], g_wfl[384 * 384];

// ---------------- helpers ----------------
__device__ __forceinline__ void cp16(void* dst, const void* src) {
    unsigned d = (unsigned)__cvta_generic_to_shared(dst);
    asm volatile("cp.async.cg.shared.global [%0], [%1], 16;" :: "r"(d), "l"(src));
}
#define CP_COMMIT() asm volatile("cp.async.commit_group;" ::: "memory")
#define CP_WAIT0()  asm volatile("cp.async.wait_group 0;" ::: "memory")

__device__ __forceinline__ void ldm_x4(uint32_t* r, uint32_t addr) {
    asm volatile("ldmatrix.sync.aligned.m8n8.x4.shared.b16 {%0,%1,%2,%3}, [%4];"
        : "=r"(r[0]), "=r"(r[1]), "=r"(r[2]), "=r"(r[3]) : "r"(addr));
}
__device__ __forceinline__ void ldm_x2t(uint32_t* r, uint32_t addr) {
    asm volatile("ldmatrix.sync.aligned.m8n8.x2.trans.shared.b16 {%0,%1}, [%2];"
        : "=r"(r[0]), "=r"(r[1]) : "r"(addr));
}
__device__ __forceinline__ void mma_bf16(float* c, const uint32_t* a, const uint32_t* b) {
    asm volatile(
        "mma.sync.aligned.m16n8k16.row.col.f32.bf16.bf16.f32 "
        "{%0,%1,%2,%3}, {%4,%5,%6,%7}, {%8,%9}, {%0,%1,%2,%3};"
        : "+f"(c[0]), "+f"(c[1]), "+f"(c[2]), "+f"(c[3])
        : "r"(a[0]), "r"(a[1]), "r"(a[2]), "r"(a[3]), "r"(b[0]), "r"(b[1]));
}

// ---------------- weight split prep: W[m][K] fp32 -> tiled [K/16][384][16] bf16 hi/lo ----------------
__global__ void wsplit_kernel(const float* __restrict__ w,
                              __nv_bfloat16* __restrict__ ht,
                              __nv_bfloat16* __restrict__ lt, int K)
{
    int idx = blockIdx.x * 256 + threadIdx.x;
    int m  = idx % 384;
    int kt = idx / 384;
    if (kt >= (K >> 4)) return;
    const float* src = w + (size_t)m * K + kt * 16;
    __nv_bfloat16* dh = ht + ((size_t)kt * 384 + m) * 16;
    __nv_bfloat16* dl = lt + ((size_t)kt * 384 + m) * 16;
#pragma unroll
    for (int j = 0; j < 16; j++) {
        float v = src[j];
        __nv_bfloat16 h = __float2bfloat16(v);
        dh[j] = h;
        dl[j] = __float2bfloat16(v - __bfloat162float(h));
    }
}

// ---------------- GroupNorm (emits xn fp32 + bf16 hi/lo planes) ----------------
__global__ __launch_bounds__(256) void groupnorm_kernel(
    const float* __restrict__ x, const float* __restrict__ gamma,
    const float* __restrict__ beta)
{
    int b = blockIdx.x / NG_;
    int g = blockIdx.x % NG_;
    size_t base = ((size_t)b * C_ + (size_t)g * CPG_) * HW_;
    const int n = CPG_ * HW_;
    int tid = threadIdx.x;

    float s = 0.f, ss = 0.f;
    for (int i = tid; i < n; i += 256) {
        float v = x[base + i];
        s += v; ss += v * v;
    }
    __shared__ float rs[256], rss[256];
    rs[tid] = s; rss[tid] = ss;
    __syncthreads();
    for (int o = 128; o > 0; o >>= 1) {
        if (tid < o) { rs[tid] += rs[tid + o]; rss[tid] += rss[tid + o]; }
        __syncthreads();
    }
    float mean = rs[0] / (float)n;
    float var  = rss[0] / (float)n - mean * mean;
    float inv  = rsqrtf(var + 1e-5f);

    for (int i = tid; i < n; i += 256) {
        int c = g * CPG_ + i / HW_;
        float v = (x[base + i] - mean) * inv;
        v = v * gamma[c] + beta[c];
        g_xn[base + i] = v;
        __nv_bfloat16 h = __float2bfloat16(v);
        g_xnh[base + i] = h;
        g_xnl[base + i] = __float2bfloat16(v - __bfloat162float(h));
    }
}

// ---------------- bf16 split tensor-core GEMM (hi/lo, 3 MMAs per product, k16) ----------------
// Y[b,m,n] = sum_k W[m,k]*B(k,n) + bias[m]
//   CONV3=false: B from bf16 planes bhp/blp [b][k][n]             (KTOT=384)
//   CONV3=true : implicit 3x3 gather from fp32 xraw, split on STS (KTOT=3456)
//   MULXN: multiply output by g_xn
// smem: AH[2]|AL[2]|BH[2]|BL[2], each plane 4096B (A: 128m x 16k bf16; B: 16k x 128n bf16)
#define AH_O(p) ((p) * 4096)
#define AL_O(p) (8192 + (p) * 4096)
#define BH_O(p) (16384 + (p) * 4096)
#define BL_O(p) (24576 + (p) * 4096)

template <int KTOT, bool CONV3, bool MULXN>
__global__ __launch_bounds__(256) void gemm_bf16_kernel(
    const __nv_bfloat16* __restrict__ whT, const __nv_bfloat16* __restrict__ wlT,
    const __nv_bfloat16* __restrict__ bhp, const __nv_bfloat16* __restrict__ blp,
    const float* __restrict__ xraw,
    const float* __restrict__ bias, float* __restrict__ Y)
{
    __shared__ __align__(16) char smem[32768];
    const uint32_t sb = (uint32_t)__cvta_generic_to_shared(smem);

    const int b  = blockIdx.z;
    const int n0 = blockIdx.x * 128;
    const int m0 = blockIdx.y * 128;
    const __nv_bfloat16* BhG = bhp + (size_t)b * C_ * HW_;
    const __nv_bfloat16* BlG = blp + (size_t)b * C_ * HW_;
    const float* Xb = xraw + (size_t)b * C_ * HW_;

    const int tid  = threadIdx.x;
    const int lane = tid & 31;
    const int wid  = tid >> 5;
    const int wm   = wid & 1;
    const int wn   = wid >> 1;
    const int g    = lane >> 2;
    const int t    = lane & 3;

    // staging mapping
    const int am = tid >> 1, ac = tid & 1;           // A: row, k-chunk
    const int bk = tid >> 4, bc = tid & 15;          // B: k-row, n-chunk
    const uint32_t aPhys = (uint32_t)((((am * 2 + ac) ^ ((am >> 2) & 1))) * 16);
    const uint32_t bPhys = (uint32_t)(bk * 256 + (((bc & 8) | ((bc ^ bk) & 7))) * 16);

    // fragment address offsets (loop-invariant)
    const int ml = lane & 15, kcl = lane >> 4;
    uint32_t aOff[4], bOff[4];
#pragma unroll
    for (int mi = 0; mi < 4; mi++) {
        int m = wm * 64 + mi * 16 + ml;
        aOff[mi] = (uint32_t)((((m * 2 + kcl) ^ ((m >> 2) & 1))) * 16);
    }
    const int kl = lane & 15;
#pragma unroll
    for (int ni = 0; ni < 4; ni++) {
        int c = wn * 4 + ni;
        int cc = (c & 8) | ((c ^ (kl & 7)) & 7);
        bOff[ni] = (uint32_t)(kl * 256 + cc * 16);
    }

    float acc[4][4][4];
#pragma unroll
    for (int mi = 0; mi < 4; mi++)
#pragma unroll
        for (int ni = 0; ni < 4; ni++)
#pragma unroll
            for (int r = 0; r < 4; r++) acc[mi][ni][r] = 0.f;

    const int NIT = KTOT / 16;
    float cv[8];

    // ---- prologue: tile 0 -> buffer 0 ----
    {
        const __nv_bfloat16* sh = whT + ((size_t)0 * 384 + m0 + am) * 16 + ac * 8;
        const __nv_bfloat16* sl = wlT + ((size_t)0 * 384 + m0 + am) * 16 + ac * 8;
        cp16(smem + AH_O(0) + aPhys, sh);
        cp16(smem + AL_O(0) + aPhys, sl);
        if (!CONV3) {
            cp16(smem + BH_O(0) + bPhys, BhG + (size_t)bk * HW_ + n0 + bc * 8);
            cp16(smem + BL_O(0) + bPhys, BlG + (size_t)bk * HW_ + n0 + bc * 8);
        }
        CP_COMMIT();
        if (CONV3) {
            const int kk = bk;
            const int ci = kk / 9, rs = kk - ci * 9;
            const int dy = rs / 3 - 1, dx = rs - (rs / 3) * 3 - 1;
            const int hh = ((n0 + bc * 8) >> 6) + dy;
            const int wb = (bc * 8) & 63;
            const float* xrow = Xb + (size_t)ci * HW_ + hh * HWDIM;
            const bool hok = (hh >= 0 && hh < HWDIM);
#pragma unroll
            for (int j = 0; j < 8; j++) {
                int w = wb + j + dx;
                cv[j] = (hok && w >= 0 && w < HWDIM) ? xrow[w] : 0.f;
            }
            uint32_t ph[4], pl[4];
#pragma unroll
            for (int jj = 0; jj < 4; jj++) {
                __nv_bfloat162 h2 = __floats2bfloat162_rn(cv[2 * jj], cv[2 * jj + 1]);
                float la = cv[2 * jj]     - __bfloat162float(h2.x);
                float lb = cv[2 * jj + 1] - __bfloat162float(h2.y);
                __nv_bfloat162 l2 = __floats2bfloat162_rn(la, lb);
                ph[jj] = *(uint32_t*)&h2;
                pl[jj] = *(uint32_t*)&l2;
            }
            *(uint4*)(smem + BH_O(0) + bPhys) = make_uint4(ph[0], ph[1], ph[2], ph[3]);
            *(uint4*)(smem + BL_O(0) + bPhys) = make_uint4(pl[0], pl[1], pl[2], pl[3]);
        }
    }

    for (int it = 0; it < NIT; it++) {
        const int p = it & 1;
        const int q = 1 - p;

        CP_WAIT0();
        __syncthreads();

        const bool next = (it + 1 < NIT);
        if (next) {
            const int kt = it + 1;
            const __nv_bfloat16* sh = whT + ((size_t)kt * 384 + m0 + am) * 16 + ac * 8;
            const __nv_bfloat16* sl = wlT + ((size_t)kt * 384 + m0 + am) * 16 + ac * 8;
            cp16(smem + AH_O(q) + aPhys, sh);
            cp16(smem + AL_O(q) + aPhys, sl);
            if (!CONV3) {
                const int k0 = kt * 16;
                cp16(smem + BH_O(q) + bPhys, BhG + (size_t)(k0 + bk) * HW_ + n0 + bc * 8);
                cp16(smem + BL_O(q) + bPhys, BlG + (size_t)(k0 + bk) * HW_ + n0 + bc * 8);
            }
            CP_COMMIT();
            if (CONV3) {
                const int kk = kt * 16 + bk;
                const int ci = kk / 9, rs = kk - ci * 9;
                const int dy = rs / 3 - 1, dx = rs - (rs / 3) * 3 - 1;
                const int hh = ((n0 + bc * 8) >> 6) + dy;
                const int wb = (bc * 8) & 63;
                const float* xrow = Xb + (size_t)ci * HW_ + hh * HWDIM;
                const bool hok = (hh >= 0 && hh < HWDIM);
#pragma unroll
                for (int j = 0; j < 8; j++) {
                    int w = wb + j + dx;
                    cv[j] = (hok && w >= 0 && w < HWDIM) ? xrow[w] : 0.f;
                }
            }
        }

        // ---- compute buffer p ----
        {
            const uint32_t aH = sb + AH_O(p), aL = sb + AL_O(p);
            const uint32_t bH = sb + BH_O(p), bL = sb + BL_O(p);

            uint32_t ah[4][4], bh[4][2], bx[4][2], al[4][4];
#pragma unroll
            for (int mi = 0; mi < 4; mi++) ldm_x4(ah[mi], aH + aOff[mi]);
#pragma unroll
            for (int ni = 0; ni < 4; ni++) ldm_x2t(bh[ni], bH + bOff[ni]);
            // term 1: hi x hi
#pragma unroll
            for (int mi = 0; mi < 4; mi++)
#pragma unroll
                for (int ni = 0; ni < 4; ni++) mma_bf16(acc[mi][ni], ah[mi], bh[ni]);
            // term 2: hi x lo
#pragma unroll
            for (int ni = 0; ni < 4; ni++) ldm_x2t(bx[ni], bL + bOff[ni]);
#pragma unroll
            for (int mi = 0; mi < 4; mi++)
#pragma unroll
                for (int ni = 0; ni < 4; ni++) mma_bf16(acc[mi][ni], ah[mi], bx[ni]);
            // term 3: lo x hi
#pragma unroll
            for (int mi = 0; mi < 4; mi++) ldm_x4(al[mi], aL + aOff[mi]);
#pragma unroll
            for (int mi = 0; mi < 4; mi++)
#pragma unroll
                for (int ni = 0; ni < 4; ni++) mma_bf16(acc[mi][ni], al[mi], bh[ni]);
        }

        if (next && CONV3) {
            uint32_t ph[4], pl[4];
#pragma unroll
            for (int jj = 0; jj < 4; jj++) {
                __nv_bfloat162 h2 = __floats2bfloat162_rn(cv[2 * jj], cv[2 * jj + 1]);
                float la = cv[2 * jj]     - __bfloat162float(h2.x);
                float lb = cv[2 * jj + 1] - __bfloat162float(h2.y);
                __nv_bfloat162 l2 = __floats2bfloat162_rn(la, lb);
                ph[jj] = *(uint32_t*)&h2;
                pl[jj] = *(uint32_t*)&l2;
            }
            *(uint4*)(smem + BH_O(q) + bPhys) = make_uint4(ph[0], ph[1], ph[2], ph[3]);
            *(uint4*)(smem + BL_O(q) + bPhys) = make_uint4(pl[0], pl[1], pl[2], pl[3]);
        }
        __syncthreads();
    }

    // ---- epilogue ----
    const size_t ybase = (size_t)b * C_ * HW_;
#pragma unroll
    for (int mi = 0; mi < 4; mi++) {
        const int r0 = m0 + wm * 64 + mi * 16 + g;
        const int r1 = r0 + 8;
        const float bi0 = bias[r0];
        const float bi1 = bias[r1];
#pragma unroll
        for (int ni = 0; ni < 4; ni++) {
            const int col = n0 + wn * 32 + ni * 8 + 2 * t;
            float2 o0 = make_float2(acc[mi][ni][0] + bi0, acc[mi][ni][1] + bi0);
            float2 o1 = make_float2(acc[mi][ni][2] + bi1, acc[mi][ni][3] + bi1);
            size_t off0 = ybase + (size_t)r0 * HW_ + col;
            size_t off1 = ybase + (size_t)r1 * HW_ + col;
            if (MULXN) {
                float2 m0v = *(const float2*)&g_xn[off0];
                float2 m1v = *(const float2*)&g_xn[off1];
                o0.x *= m0v.x; o0.y *= m0v.y;
                o1.x *= m1v.x; o1.y *= m1v.y;
            }
            *(float2*)&Y[off0] = o0;
            *(float2*)&Y[off1] = o1;
        }
    }
}

// ---------------- FFT-domain circular conv per (b,c) ----------------
#define FFT_SMEM_FLOATS (128 + 4096 + 3 * 2 * 4096)
#define FFT_SMEM_BYTES  (FFT_SMEM_FLOATS * 4)   // 115200

__global__ __launch_bounds__(512) void fft_attn_kernel(
    float* __restrict__ Aq /* in: q, out: A */, const float* __restrict__ Kk)
{
    extern __shared__ float smf[];
    float2* tw  = (float2*)smf;
    float*  inb = smf + 128;
    float2* T   = (float2*)(smf + 128 + 4096);
    float2* Fq  = T + 4096;
    float2* Fk  = Fq + 4096;

    int tid = threadIdx.x;
    size_t base = (size_t)blockIdx.x * HW_;
    int l  = tid & 63;
    int jb = (tid >> 6) * 8;

    if (tid < 64) {
        float ang = -2.f * PI_F * (float)tid / 64.f;
        tw[tid] = make_float2(cosf(ang), sinf(ang));
    }
    __syncthreads();

    for (int field = 0; field < 2; field++) {
        const float* src = (field == 0) ? (Aq + base) : (Kk + base);
        float2* dst = (field == 0) ? Fq : Fk;

        for (int i = tid; i < 4096; i += 512) inb[i] = src[i];
        __syncthreads();

        {
            float ar[8], ai[8];
#pragma unroll
            for (int jj = 0; jj < 8; jj++) { ar[jj] = 0.f; ai[jj] = 0.f; }
            for (int m = 0; m < 64; m++) {
                float xv = inb[m * 64 + l];
#pragma unroll
                for (int jj = 0; jj < 8; jj++) {
                    float2 c = tw[((jb + jj) * m) & 63];
                    ar[jj] += c.x * xv;
                    ai[jj] += c.y * xv;
                }
            }
#pragma unroll
            for (int jj = 0; jj < 8; jj++)
                T[(jb + jj) * 64 + l] = make_float2(ar[jj], ai[jj]);
        }
        __syncthreads();

        {
            float2 wl = tw[l];
            float cr = 1.f, ci = 0.f;
            float ar[8], ai[8];
#pragma unroll
            for (int jj = 0; jj < 8; jj++) { ar[jj] = 0.f; ai[jj] = 0.f; }
            for (int m = 0; m < 64; m++) {
#pragma unroll
                for (int jj = 0; jj < 8; jj++) {
                    float2 t = T[(jb + jj) * 64 + m];
                    ar[jj] += t.x * cr - t.y * ci;
                    ai[jj] += t.x * ci + t.y * cr;
                }
                float nr = cr * wl.x - ci * wl.y;
                ci = cr * wl.y + ci * wl.x;
                cr = nr;
            }
#pragma unroll
            for (int jj = 0; jj < 8; jj++)
                dst[(jb + jj) * 64 + l] = make_float2(ar[jj], ai[jj]);
        }
        __syncthreads();
    }

    for (int i = tid; i < 4096; i += 512) {
        float2 a = Fq[i], bq = Fk[i];
        Fq[i] = make_float2(a.x * bq.x - a.y * bq.y, a.x * bq.y + a.y * bq.x);
    }
    __syncthreads();

    {
        float ar[8], ai[8];
#pragma unroll
        for (int jj = 0; jj < 8; jj++) { ar[jj] = 0.f; ai[jj] = 0.f; }
        for (int m = 0; m < 64; m++) {
            float2 p = Fq[m * 64 + l];
#pragma unroll
            for (int jj = 0; jj < 8; jj++) {
                float2 c = tw[((jb + jj) * m) & 63];
                ar[jj] += c.x * p.x + c.y * p.y;
                ai[jj] += c.x * p.y - c.y * p.x;
            }
        }
#pragma unroll
        for (int jj = 0; jj < 8; jj++)
            T[(jb + jj) * 64 + l] = make_float2(ar[jj], ai[jj]);
    }
    __syncthreads();

    {
        float2 wl = tw[l];
        float cr = 1.f, ci = 0.f;
        float ar[8];
#pragma unroll
        for (int jj = 0; jj < 8; jj++) ar[jj] = 0.f;
        for (int m = 0; m < 64; m++) {
#pragma unroll
            for (int jj = 0; jj < 8; jj++) {
                float2 t = T[(jb + jj) * 64 + m];
                ar[jj] += t.x * cr + t.y * ci;
            }
            float nr = cr * wl.x - ci * wl.y;
            ci = cr * wl.y + ci * wl.x;
            cr = nr;
        }
#pragma unroll
        for (int jj = 0; jj < 8; jj++)
            Aq[base + (size_t)(jb + jj) * 64 + l] = ar[jj] * (1.f / 4096.f);
    }
}

// ---------------- top-k(512) + masked softmax + v-mul -> bf16 hi/lo planes ----------------
__device__ __forceinline__ unsigned f2ord(float f) {
    unsigned b = __float_as_uint(f);
    return (b & 0x80000000u) ? ~b : (b | 0x80000000u);
}
__device__ __forceinline__ float ord2f(unsigned u) {
    unsigned b = (u & 0x80000000u) ? (u ^ 0x80000000u) : ~u;
    return __uint_as_float(b);
}

__global__ __launch_bounds__(256) void topk_softmax_kernel(
    const float* __restrict__ A, const float* __restrict__ V,
    __nv_bfloat16* __restrict__ Hout, __nv_bfloat16* __restrict__ Lout)
{
    __shared__ unsigned ua[4096];
    __shared__ unsigned hist[256];
    __shared__ float redf[256];
    __shared__ unsigned s_prefix;
    __shared__ int s_kk;
    __shared__ float s_maxf;

    int tid = threadIdx.x;
    size_t base = (size_t)blockIdx.x * HW_;

    unsigned mymax = 0u;
    for (int i = tid; i < 4096; i += 256) {
        unsigned u = f2ord(A[base + i]);
        ua[i] = u;
        mymax = max(mymax, u);
    }
    hist[tid] = mymax;
    __syncthreads();
    for (int o = 128; o > 0; o >>= 1) {
        if (tid < o) hist[tid] = max(hist[tid], hist[tid + o]);
        __syncthreads();
    }
    if (tid == 0) {
        s_maxf = ord2f(hist[0]);
        s_kk = KTOP_;
        s_prefix = 0u;
    }
    __syncthreads();

    for (int level = 3; level >= 0; level--) {
        hist[tid] = 0u;
        __syncthreads();
        int shift = level * 8;
        unsigned maskhi = (level == 3) ? 0u : (0xFFFFFFFFu << (shift + 8));
        unsigned prefix = s_prefix;
        for (int i = tid; i < 4096; i += 256) {
            unsigned u = ua[i];
            if ((u & maskhi) == prefix)
                atomicAdd(&hist[(u >> shift) & 255], 1u);
        }
        __syncthreads();
        if (tid == 0) {
            int kk = s_kk;
            unsigned cum = 0;
            int d = 255;
            for (; d >= 0; d--) {
                unsigned c = hist[d];
                if (cum + c >= (unsigned)kk) break;
                cum += c;
            }
            if (d < 0) d = 0;
            s_kk = kk - (int)cum;
            s_prefix = prefix | ((unsigned)d << shift);
        }
        __syncthreads();
    }

    unsigned thr = s_prefix;
    float maxf = s_maxf;

    float ssum = 0.f;
    for (int i = tid; i < 4096; i += 256) {
        unsigned u = ua[i];
        if (u >= thr) ssum += expf(ord2f(u) - maxf);
    }
    redf[tid] = ssum;
    __syncthreads();
    for (int o = 128; o > 0; o >>= 1) {
        if (tid < o) redf[tid] += redf[tid + o];
        __syncthreads();
    }
    float inv = 1.f / redf[0];

    for (int i = tid; i < 4096; i += 256) {
        unsigned u = ua[i];
        float o = 0.f;
        if (u >= thr) o = V[base + i] * expf(ord2f(u) - maxf) * inv;
        __nv_bfloat16 h = __float2bfloat16(o);
        Hout[base + i] = h;
        Lout[base + i] = __float2bfloat16(o - __bfloat162float(h));
    }
}

// ---------------- launch ----------------
extern "C" void kernel_launch(void* const* d_in, const int* in_sizes, int n_in,
                              void* d_out, int out_size)
{
    const float* x     = (const float*)d_in[0];
    const float* gamma = (const float*)d_in[1];
    const float* beta  = (const float*)d_in[2];
    const float* wq    = (const float*)d_in[3];
    const float* bq    = (const float*)d_in[4];
    const float* wk    = (const float*)d_in[5];
    const float* bk    = (const float*)d_in[6];
    const float* wv    = (const float*)d_in[7];
    const float* bv    = (const float*)d_in[8];
    const float* wf    = (const float*)d_in[9];
    const float* bf    = (const float*)d_in[10];
    float* out = (float*)d_out;

    void *pxn, *pxnh, *pxnl, *pq, *pk, *pv, *pf4h, *pf4l;
    void *pwkh, *pwkl, *pwqh, *pwql, *pwvh, *pwvl, *pwfh, *pwfl;
    cudaGetSymbolAddress(&pxn,  g_xn);
    cudaGetSymbolAddress(&pxnh, g_xnh);
    cudaGetSymbolAddress(&pxnl, g_xnl);
    cudaGetSymbolAddress(&pq,   g_q);
    cudaGetSymbolAddress(&pk,   g_k);
    cudaGetSymbolAddress(&pv,   g_v);
    cudaGetSymbolAddress(&pf4h, g_f4h);
    cudaGetSymbolAddress(&pf4l, g_f4l);
    cudaGetSymbolAddress(&pwkh, g_wkh);
    cudaGetSymbolAddress(&pwkl, g_wkl);
    cudaGetSymbolAddress(&pwqh, g_wqh);
    cudaGetSymbolAddress(&pwql, g_wql);
    cudaGetSymbolAddress(&pwvh, g_wvh);
    cudaGetSymbolAddress(&pwvl, g_wvl);
    cudaGetSymbolAddress(&pwfh, g_wfh);
    cudaGetSymbolAddress(&pwfl, g_wfl);

    cudaFuncSetAttribute(fft_attn_kernel,
                         cudaFuncAttributeMaxDynamicSharedMemorySize, FFT_SMEM_BYTES);

    // 0. weight split prep (tiled bf16 hi/lo)
    wsplit_kernel<<<36,  256>>>(wq, (__nv_bfloat16*)pwqh, (__nv_bfloat16*)pwql, 384);
    wsplit_kernel<<<36,  256>>>(wv, (__nv_bfloat16*)pwvh, (__nv_bfloat16*)pwvl, 384);
    wsplit_kernel<<<36,  256>>>(wf, (__nv_bfloat16*)pwfh, (__nv_bfloat16*)pwfl, 384);
    wsplit_kernel<<<324, 256>>>(wk, (__nv_bfloat16*)pwkh, (__nv_bfloat16*)pwkl, 3456);

    // 1. GroupNorm (+ bf16 hi/lo planes)
    groupnorm_kernel<<<B_ * NG_, 256>>>(x, gamma, beta);

    // 2-4. q / v (1x1) and k (3x3) projections
    dim3 gg(HW_ / 128, C_ / 128, B_);
    gemm_bf16_kernel<C_, false, false><<<gg, 256>>>(
        (const __nv_bfloat16*)pwqh, (const __nv_bfloat16*)pwql,
        (const __nv_bfloat16*)pxnh, (const __nv_bfloat16*)pxnl,
        (const float*)pxn, bq, (float*)pq);
    gemm_bf16_kernel<C_, false, false><<<gg, 256>>>(
        (const __nv_bfloat16*)pwvh, (const __nv_bfloat16*)pwvl,
        (const __nv_bfloat16*)pxnh, (const __nv_bfloat16*)pxnl,
        (const float*)pxn, bv, (float*)pv);
    gemm_bf16_kernel<C_ * 9, true, false><<<gg, 256>>>(
        (const __nv_bfloat16*)pwkh, (const __nv_bfloat16*)pwkl,
        (const __nv_bfloat16*)pxnh, (const __nv_bfloat16*)pxnl,
        (const float*)pxn, bk, (float*)pk);

    // 5. FFT circular conv: A (into g_q)
    fft_attn_kernel<<<B_ * C_, 512, FFT_SMEM_BYTES>>>((float*)pq, (const float*)pk);

    // 6. top-k + softmax + v-mul -> bf16 hi/lo F4 planes
    topk_softmax_kernel<<<B_ * C_, 256>>>((const float*)pq, (const float*)pv,
                                          (__nv_bfloat16*)pf4h, (__nv_bfloat16*)pf4l);

    // 7. final 1x1 conv with xn-multiply epilogue
    gemm_bf16_kernel<C_, false, true><<<gg, 256>>>(
        (const __nv_bfloat16*)pwfh, (const __nv_bfloat16*)pwfl,
        (const __nv_bfloat16*)pf4h, (const __nv_bfloat16*)pf4l,
        (const float*)pxn, bf, out);
}

// round 7
// speedup vs baseline: 2.7654x; 1.1364x over previous
#include <cuda_runtime.h>
#include <cuda_bf16.h>
#include <math.h>
#include <stdint.h>

#define B_    8
#define C_    384
#define HW_   4096
#define HWDIM 64
#define NG_   32
#define CPG_  12
#define KTOP_ 512
#define PI_F  3.14159265358979323846f

// ---------------- scratch (device globals; no allocation) ----------------
__device__ float g_xn [(size_t)B_ * C_ * HW_];
__device__ float g_q  [(size_t)B_ * C_ * HW_];   // q -> A (FFT out)
__device__ float g_k  [(size_t)B_ * C_ * HW_];   // 3x3-conv k output
__device__ float g_v  [(size_t)B_ * C_ * HW_];   // v output
__device__ __nv_bfloat16 g_xnh[(size_t)B_ * C_ * HW_];
__device__ __nv_bfloat16 g_xnl[(size_t)B_ * C_ * HW_];
__device__ __nv_bfloat16 g_f4h[(size_t)B_ * C_ * HW_];
__device__ __nv_bfloat16 g_f4l[(size_t)B_ * C_ * HW_];
// tiled split weight planes: [K/16][384][16] bf16
__device__ __nv_bfloat16 g_wkh[(size_t)384 * 3456];
__device__ __nv_bfloat16 g_wkl[(size_t)384 * 3456];
__device__ __nv_bfloat16 g_wqh[384 * 384], g_wql[384 * 384];
__device__ __nv_bfloat16 g_wvh[384 * 384], g_wvl[384 * 384];
__device__ __nv_bfloat16 g_wfh[384 * 384], g_wfl[384 * 384];

// ---------------- helpers ----------------
__device__ __forceinline__ void cp16(void* dst, const void* src) {
    unsigned d = (unsigned)__cvta_generic_to_shared(dst);
    asm volatile("cp.async.cg.shared.global [%0], [%1], 16;" :: "r"(d), "l"(src));
}
#define CP_COMMIT() asm volatile("cp.async.commit_group;" ::: "memory")
#define CP_WAIT0()  asm volatile("cp.async.wait_group 0;" ::: "memory")

__device__ __forceinline__ void ldm_x4(uint32_t* r, uint32_t addr) {
    asm volatile("ldmatrix.sync.aligned.m8n8.x4.shared.b16 {%0,%1,%2,%3}, [%4];"
        : "=r"(r[0]), "=r"(r[1]), "=r"(r[2]), "=r"(r[3]) : "r"(addr));
}
__device__ __forceinline__ void ldm_x2t(uint32_t* r, uint32_t addr) {
    asm volatile("ldmatrix.sync.aligned.m8n8.x2.trans.shared.b16 {%0,%1}, [%2];"
        : "=r"(r[0]), "=r"(r[1]) : "r"(addr));
}
__device__ __forceinline__ void mma_bf16(float* c, const uint32_t* a, const uint32_t* b) {
    asm volatile(
        "mma.sync.aligned.m16n8k16.row.col.f32.bf16.bf16.f32 "
        "{%0,%1,%2,%3}, {%4,%5,%6,%7}, {%8,%9}, {%0,%1,%2,%3};"
        : "+f"(c[0]), "+f"(c[1]), "+f"(c[2]), "+f"(c[3])
        : "r"(a[0]), "r"(a[1]), "r"(a[2]), "r"(a[3]), "r"(b[0]), "r"(b[1]));
}

// ---------------- weight split prep (packed 16B stores) ----------------
__global__ void wsplit_kernel(const float* __restrict__ w,
                              __nv_bfloat16* __restrict__ ht,
                              __nv_bfloat16* __restrict__ lt, int K)
{
    int idx = blockIdx.x * 256 + threadIdx.x;
    int m  = idx % 384;
    int kt = idx / 384;
    if (kt >= (K >> 4)) return;
    const float4* src = (const float4*)(w + (size_t)m * K + kt * 16);
    uint4 ho[2], lo[2];
    uint32_t* hw = (uint32_t*)ho;
    uint32_t* lw = (uint32_t*)lo;
#pragma unroll
    for (int j = 0; j < 4; j++) {
        float4 v = src[j];
        __nv_bfloat162 h0 = __floats2bfloat162_rn(v.x, v.y);
        __nv_bfloat162 h1 = __floats2bfloat162_rn(v.z, v.w);
        __nv_bfloat162 l0 = __floats2bfloat162_rn(v.x - __bfloat162float(h0.x),
                                                  v.y - __bfloat162float(h0.y));
        __nv_bfloat162 l1 = __floats2bfloat162_rn(v.z - __bfloat162float(h1.x),
                                                  v.w - __bfloat162float(h1.y));
        hw[2 * j]     = *(uint32_t*)&h0;
        hw[2 * j + 1] = *(uint32_t*)&h1;
        lw[2 * j]     = *(uint32_t*)&l0;
        lw[2 * j + 1] = *(uint32_t*)&l1;
    }
    uint4* dh = (uint4*)(ht + ((size_t)kt * 384 + m) * 16);
    uint4* dl = (uint4*)(lt + ((size_t)kt * 384 + m) * 16);
    dh[0] = ho[0]; dh[1] = ho[1];
    dl[0] = lo[0]; dl[1] = lo[1];
}

// ---------------- GroupNorm (vectorized, emits xn fp32 + bf16 hi/lo) ----------------
__global__ __launch_bounds__(256) void groupnorm_kernel(
    const float* __restrict__ x, const float* __restrict__ gamma,
    const float* __restrict__ beta)
{
    int b = blockIdx.x / NG_;
    int g = blockIdx.x % NG_;
    size_t base = ((size_t)b * C_ + (size_t)g * CPG_) * HW_;
    const int n = CPG_ * HW_;
    int tid = threadIdx.x;

    float s = 0.f, ss = 0.f;
    for (int i = tid * 4; i < n; i += 1024) {
        float4 v = *(const float4*)&x[base + i];
        s  += v.x + v.y + v.z + v.w;
        ss += v.x * v.x + v.y * v.y + v.z * v.z + v.w * v.w;
    }
    __shared__ float rs[256], rss[256];
    rs[tid] = s; rss[tid] = ss;
    __syncthreads();
    for (int o = 128; o > 0; o >>= 1) {
        if (tid < o) { rs[tid] += rs[tid + o]; rss[tid] += rss[tid + o]; }
        __syncthreads();
    }
    float mean = rs[0] / (float)n;
    float var  = rss[0] / (float)n - mean * mean;
    float inv  = rsqrtf(var + 1e-5f);

    for (int i = tid * 4; i < n; i += 1024) {
        int c = g * CPG_ + i / HW_;
        float ga = gamma[c], be = beta[c];
        float4 v = *(const float4*)&x[base + i];
        v.x = (v.x - mean) * inv * ga + be;
        v.y = (v.y - mean) * inv * ga + be;
        v.z = (v.z - mean) * inv * ga + be;
        v.w = (v.w - mean) * inv * ga + be;
        *(float4*)&g_xn[base + i] = v;
        __nv_bfloat162 h0 = __floats2bfloat162_rn(v.x, v.y);
        __nv_bfloat162 h1 = __floats2bfloat162_rn(v.z, v.w);
        __nv_bfloat162 l0 = __floats2bfloat162_rn(v.x - __bfloat162float(h0.x),
                                                  v.y - __bfloat162float(h0.y));
        __nv_bfloat162 l1 = __floats2bfloat162_rn(v.z - __bfloat162float(h1.x),
                                                  v.w - __bfloat162float(h1.y));
        *(__nv_bfloat162*)&g_xnh[base + i]     = h0;
        *(__nv_bfloat162*)&g_xnh[base + i + 2] = h1;
        *(__nv_bfloat162*)&g_xnl[base + i]     = l0;
        *(__nv_bfloat162*)&g_xnl[base + i + 2] = l1;
    }
}

// ---------------- bf16 split tensor-core GEMM (unchanged from R6) ----------------
#define AH_O(p) ((p) * 4096)
#define AL_O(p) (8192 + (p) * 4096)
#define BH_O(p) (16384 + (p) * 4096)
#define BL_O(p) (24576 + (p) * 4096)

template <int KTOT, bool CONV3, bool MULXN>
__global__ __launch_bounds__(256) void gemm_bf16_kernel(
    const __nv_bfloat16* __restrict__ whT, const __nv_bfloat16* __restrict__ wlT,
    const __nv_bfloat16* __restrict__ bhp, const __nv_bfloat16* __restrict__ blp,
    const float* __restrict__ xraw,
    const float* __restrict__ bias, float* __restrict__ Y)
{
    __shared__ __align__(16) char smem[32768];
    const uint32_t sb = (uint32_t)__cvta_generic_to_shared(smem);

    const int b  = blockIdx.z;
    const int n0 = blockIdx.x * 128;
    const int m0 = blockIdx.y * 128;
    const __nv_bfloat16* BhG = bhp + (size_t)b * C_ * HW_;
    const __nv_bfloat16* BlG = blp + (size_t)b * C_ * HW_;
    const float* Xb = xraw + (size_t)b * C_ * HW_;

    const int tid  = threadIdx.x;
    const int lane = tid & 31;
    const int wid  = tid >> 5;
    const int wm   = wid & 1;
    const int wn   = wid >> 1;
    const int g    = lane >> 2;
    const int t    = lane & 3;

    const int am = tid >> 1, ac = tid & 1;
    const int bk = tid >> 4, bc = tid & 15;
    const uint32_t aPhys = (uint32_t)((((am * 2 + ac) ^ ((am >> 2) & 1))) * 16);
    const uint32_t bPhys = (uint32_t)(bk * 256 + (((bc & 8) | ((bc ^ bk) & 7))) * 16);

    const int ml = lane & 15, kcl = lane >> 4;
    uint32_t aOff[4], bOff[4];
#pragma unroll
    for (int mi = 0; mi < 4; mi++) {
        int m = wm * 64 + mi * 16 + ml;
        aOff[mi] = (uint32_t)((((m * 2 + kcl) ^ ((m >> 2) & 1))) * 16);
    }
    const int kl = lane & 15;
#pragma unroll
    for (int ni = 0; ni < 4; ni++) {
        int c = wn * 4 + ni;
        int cc = (c & 8) | ((c ^ (kl & 7)) & 7);
        bOff[ni] = (uint32_t)(kl * 256 + cc * 16);
    }

    float acc[4][4][4];
#pragma unroll
    for (int mi = 0; mi < 4; mi++)
#pragma unroll
        for (int ni = 0; ni < 4; ni++)
#pragma unroll
            for (int r = 0; r < 4; r++) acc[mi][ni][r] = 0.f;

    const int NIT = KTOT / 16;
    float cv[8];

    {
        const __nv_bfloat16* sh = whT + ((size_t)0 * 384 + m0 + am) * 16 + ac * 8;
        const __nv_bfloat16* sl = wlT + ((size_t)0 * 384 + m0 + am) * 16 + ac * 8;
        cp16(smem + AH_O(0) + aPhys, sh);
        cp16(smem + AL_O(0) + aPhys, sl);
        if (!CONV3) {
            cp16(smem + BH_O(0) + bPhys, BhG + (size_t)bk * HW_ + n0 + bc * 8);
            cp16(smem + BL_O(0) + bPhys, BlG + (size_t)bk * HW_ + n0 + bc * 8);
        }
        CP_COMMIT();
        if (CONV3) {
            const int kk = bk;
            const int ci = kk / 9, rs = kk - ci * 9;
            const int dy = rs / 3 - 1, dx = rs - (rs / 3) * 3 - 1;
            const int hh = ((n0 + bc * 8) >> 6) + dy;
            const int wb = (bc * 8) & 63;
            const float* xrow = Xb + (size_t)ci * HW_ + hh * HWDIM;
            const bool hok = (hh >= 0 && hh < HWDIM);
#pragma unroll
            for (int j = 0; j < 8; j++) {
                int w = wb + j + dx;
                cv[j] = (hok && w >= 0 && w < HWDIM) ? xrow[w] : 0.f;
            }
            uint32_t ph[4], pl[4];
#pragma unroll
            for (int jj = 0; jj < 4; jj++) {
                __nv_bfloat162 h2 = __floats2bfloat162_rn(cv[2 * jj], cv[2 * jj + 1]);
                float la = cv[2 * jj]     - __bfloat162float(h2.x);
                float lb = cv[2 * jj + 1] - __bfloat162float(h2.y);
                __nv_bfloat162 l2 = __floats2bfloat162_rn(la, lb);
                ph[jj] = *(uint32_t*)&h2;
                pl[jj] = *(uint32_t*)&l2;
            }
            *(uint4*)(smem + BH_O(0) + bPhys) = make_uint4(ph[0], ph[1], ph[2], ph[3]);
            *(uint4*)(smem + BL_O(0) + bPhys) = make_uint4(pl[0], pl[1], pl[2], pl[3]);
        }
    }

    for (int it = 0; it < NIT; it++) {
        const int p = it & 1;
        const int q = 1 - p;

        CP_WAIT0();
        __syncthreads();

        const bool next = (it + 1 < NIT);
        if (next) {
            const int kt = it + 1;
            const __nv_bfloat16* sh = whT + ((size_t)kt * 384 + m0 + am) * 16 + ac * 8;
            const __nv_bfloat16* sl = wlT + ((size_t)kt * 384 + m0 + am) * 16 + ac * 8;
            cp16(smem + AH_O(q) + aPhys, sh);
            cp16(smem + AL_O(q) + aPhys, sl);
            if (!CONV3) {
                const int k0 = kt * 16;
                cp16(smem + BH_O(q) + bPhys, BhG + (size_t)(k0 + bk) * HW_ + n0 + bc * 8);
                cp16(smem + BL_O(q) + bPhys, BlG + (size_t)(k0 + bk) * HW_ + n0 + bc * 8);
            }
            CP_COMMIT();
            if (CONV3) {
                const int kk = kt * 16 + bk;
                const int ci = kk / 9, rs = kk - ci * 9;
                const int dy = rs / 3 - 1, dx = rs - (rs / 3) * 3 - 1;
                const int hh = ((n0 + bc * 8) >> 6) + dy;
                const int wb = (bc * 8) & 63;
                const float* xrow = Xb + (size_t)ci * HW_ + hh * HWDIM;
                const bool hok = (hh >= 0 && hh < HWDIM);
#pragma unroll
                for (int j = 0; j < 8; j++) {
                    int w = wb + j + dx;
                    cv[j] = (hok && w >= 0 && w < HWDIM) ? xrow[w] : 0.f;
                }
            }
        }

        {
            const uint32_t aH = sb + AH_O(p), aL = sb + AL_O(p);
            const uint32_t bH = sb + BH_O(p), bL = sb + BL_O(p);

            uint32_t ah[4][4], bh[4][2], bx[4][2], al[4][4];
#pragma unroll
            for (int mi = 0; mi < 4; mi++) ldm_x4(ah[mi], aH + aOff[mi]);
#pragma unroll
            for (int ni = 0; ni < 4; ni++) ldm_x2t(bh[ni], bH + bOff[ni]);
#pragma unroll
            for (int mi = 0; mi < 4; mi++)
#pragma unroll
                for (int ni = 0; ni < 4; ni++) mma_bf16(acc[mi][ni], ah[mi], bh[ni]);
#pragma unroll
            for (int ni = 0; ni < 4; ni++) ldm_x2t(bx[ni], bL + bOff[ni]);
#pragma unroll
            for (int mi = 0; mi < 4; mi++)
#pragma unroll
                for (int ni = 0; ni < 4; ni++) mma_bf16(acc[mi][ni], ah[mi], bx[ni]);
#pragma unroll
            for (int mi = 0; mi < 4; mi++) ldm_x4(al[mi], aL + aOff[mi]);
#pragma unroll
            for (int mi = 0; mi < 4; mi++)
#pragma unroll
                for (int ni = 0; ni < 4; ni++) mma_bf16(acc[mi][ni], al[mi], bh[ni]);
        }

        if (next && CONV3) {
            uint32_t ph[4], pl[4];
#pragma unroll
            for (int jj = 0; jj < 4; jj++) {
                __nv_bfloat162 h2 = __floats2bfloat162_rn(cv[2 * jj], cv[2 * jj + 1]);
                float la = cv[2 * jj]     - __bfloat162float(h2.x);
                float lb = cv[2 * jj + 1] - __bfloat162float(h2.y);
                __nv_bfloat162 l2 = __floats2bfloat162_rn(la, lb);
                ph[jj] = *(uint32_t*)&h2;
                pl[jj] = *(uint32_t*)&l2;
            }
            *(uint4*)(smem + BH_O(q) + bPhys) = make_uint4(ph[0], ph[1], ph[2], ph[3]);
            *(uint4*)(smem + BL_O(q) + bPhys) = make_uint4(pl[0], pl[1], pl[2], pl[3]);
        }
        __syncthreads();
    }

    const size_t ybase = (size_t)b * C_ * HW_;
#pragma unroll
    for (int mi = 0; mi < 4; mi++) {
        const int r0 = m0 + wm * 64 + mi * 16 + g;
        const int r1 = r0 + 8;
        const float bi0 = bias[r0];
        const float bi1 = bias[r1];
#pragma unroll
        for (int ni = 0; ni < 4; ni++) {
            const int col = n0 + wn * 32 + ni * 8 + 2 * t;
            float2 o0 = make_float2(acc[mi][ni][0] + bi0, acc[mi][ni][1] + bi0);
            float2 o1 = make_float2(acc[mi][ni][2] + bi1, acc[mi][ni][3] + bi1);
            size_t off0 = ybase + (size_t)r0 * HW_ + col;
            size_t off1 = ybase + (size_t)r1 * HW_ + col;
            if (MULXN) {
                float2 m0v = *(const float2*)&g_xn[off0];
                float2 m1v = *(const float2*)&g_xn[off1];
                o0.x *= m0v.x; o0.y *= m0v.y;
                o1.x *= m1v.x; o1.y *= m1v.y;
            }
            *(float2*)&Y[off0] = o0;
            *(float2*)&Y[off1] = o1;
        }
    }
}

// ---------------- packed FFT circular conv per (b,c) ----------------
// z = q + i*k ; Z = FFT2(z) ; P(u) = Fq*Fk = -i(Z(u)^2 - conj(Z(-u)^2))/4
// A = Re(IFFT2(P)) -> scale 1/(4*4096)
#define FFT2_SMEM_BYTES (512 + 2 * 4096 * 8)   // 66048

__global__ __launch_bounds__(512) void fft_attn_packed(
    float* __restrict__ Aq /* in: q, out: A */, const float* __restrict__ Kk)
{
    extern __shared__ float smf[];
    float2* tw = (float2*)smf;           // 64 twiddles
    float2* Z  = (float2*)(smf + 128);   // 4096 complex
    float2* T  = Z + 4096;               // 4096 complex

    int tid = threadIdx.x;
    size_t base = (size_t)blockIdx.x * HW_;
    int l  = tid & 63;
    int jb = (tid >> 6) * 8;

    if (tid < 64) {
        float ang = -2.f * PI_F * (float)tid / 64.f;
        tw[tid] = make_float2(cosf(ang), sinf(ang));
    }
    __syncthreads();

    // load packed field
    for (int i = tid; i < 4096; i += 512)
        Z[i] = make_float2(Aq[base + i], Kk[base + i]);
    __syncthreads();

    // forward stage A: T[j][l] = sum_m tw[(jm)&63] * Z[m][l]  (complex*complex)
    {
        float ar[8], ai[8];
#pragma unroll
        for (int jj = 0; jj < 8; jj++) { ar[jj] = 0.f; ai[jj] = 0.f; }
        for (int m = 0; m < 64; m++) {
            float2 z = Z[m * 64 + l];
#pragma unroll
            for (int jj = 0; jj < 8; jj++) {
                float2 c = tw[((jb + jj) * m) & 63];
                ar[jj] += c.x * z.x - c.y * z.y;
                ai[jj] += c.x * z.y + c.y * z.x;
            }
        }
#pragma unroll
        for (int jj = 0; jj < 8; jj++)
            T[(jb + jj) * 64 + l] = make_float2(ar[jj], ai[jj]);
    }
    __syncthreads();

    // forward stage B: Z[j][l] = sum_m T[j][m] * w_l^m (register rotation)
    {
        float2 wl = tw[l];
        float cr = 1.f, ci = 0.f;
        float ar[8], ai[8];
#pragma unroll
        for (int jj = 0; jj < 8; jj++) { ar[jj] = 0.f; ai[jj] = 0.f; }
        for (int m = 0; m < 64; m++) {
#pragma unroll
            for (int jj = 0; jj < 8; jj++) {
                float2 t = T[(jb + jj) * 64 + m];
                ar[jj] += t.x * cr - t.y * ci;
                ai[jj] += t.x * ci + t.y * cr;
            }
            float nr = cr * wl.x - ci * wl.y;
            ci = cr * wl.y + ci * wl.x;
            cr = nr;
        }
#pragma unroll
        for (int jj = 0; jj < 8; jj++)
            Z[(jb + jj) * 64 + l] = make_float2(ar[jj], ai[jj]);
    }
    __syncthreads();

    // product: T[u] = (Dy, -Dx) with D = Z(u)^2 - conj(Z(-u)^2); 1/4 folded into final scale
    for (int i = tid; i < 4096; i += 512) {
        int u1 = i >> 6, u2 = i & 63;
        int ineg = (((64 - u1) & 63) << 6) | ((64 - u2) & 63);
        float2 s = Z[i], t2 = Z[ineg];
        float s2x = s.x * s.x - s.y * s.y;
        float s2y = 2.f * s.x * s.y;
        float t2x = t2.x * t2.x - t2.y * t2.y;
        float t2y = 2.f * t2.x * t2.y;
        float Dx = s2x - t2x;
        float Dy = s2y + t2y;
        T[i] = make_float2(Dy, -Dx);
    }
    __syncthreads();

    // inverse stage A: Z[j][l] = sum_m conj(tw[(jm)&63]) * T[m][l]
    {
        float ar[8], ai[8];
#pragma unroll
        for (int jj = 0; jj < 8; jj++) { ar[jj] = 0.f; ai[jj] = 0.f; }
        for (int m = 0; m < 64; m++) {
            float2 p = T[m * 64 + l];
#pragma unroll
            for (int jj = 0; jj < 8; jj++) {
                float2 c = tw[((jb + jj) * m) & 63];
                ar[jj] += c.x * p.x + c.y * p.y;
                ai[jj] += c.x * p.y - c.y * p.x;
            }
        }
#pragma unroll
        for (int jj = 0; jj < 8; jj++)
            Z[(jb + jj) * 64 + l] = make_float2(ar[jj], ai[jj]);
    }
    __syncthreads();

    // inverse stage B (real part): A[j][l] = scale * sum_m Re(Z[j][m] * conj(w_l^m))
    {
        float2 wl = tw[l];
        float cr = 1.f, ci = 0.f;
        float ar[8];
#pragma unroll
        for (int jj = 0; jj < 8; jj++) ar[jj] = 0.f;
        for (int m = 0; m < 64; m++) {
#pragma unroll
            for (int jj = 0; jj < 8; jj++) {
                float2 t = Z[(jb + jj) * 64 + m];
                ar[jj] += t.x * cr + t.y * ci;
            }
            float nr = cr * wl.x - ci * wl.y;
            ci = cr * wl.y + ci * wl.x;
            cr = nr;
        }
#pragma unroll
        for (int jj = 0; jj < 8; jj++)
            Aq[base + (size_t)(jb + jj) * 64 + l] = ar[jj] * (1.f / 16384.f);
    }
}

// ---------------- top-k(512) + masked softmax + v-mul -> bf16 hi/lo planes ----------------
__device__ __forceinline__ unsigned f2ord(float f) {
    unsigned b = __float_as_uint(f);
    return (b & 0x80000000u) ? ~b : (b | 0x80000000u);
}
__device__ __forceinline__ float ord2f(unsigned u) {
    unsigned b = (u & 0x80000000u) ? (u ^ 0x80000000u) : ~u;
    return __uint_as_float(b);
}

__global__ __launch_bounds__(256) void topk_softmax_kernel(
    const float* __restrict__ A, const float* __restrict__ V,
    __nv_bfloat16* __restrict__ Hout, __nv_bfloat16* __restrict__ Lout)
{
    __shared__ unsigned ua[4096];
    __shared__ unsigned hist[256];
    __shared__ float redf[256];
    __shared__ unsigned s_prefix;
    __shared__ int s_kk;
    __shared__ float s_maxf;

    int tid = threadIdx.x;
    size_t base = (size_t)blockIdx.x * HW_;

    unsigned mymax = 0u;
    for (int i = tid; i < 4096; i += 256) {
        unsigned u = f2ord(A[base + i]);
        ua[i] = u;
        mymax = max(mymax, u);
    }
    hist[tid] = mymax;
    __syncthreads();
    for (int o = 128; o > 0; o >>= 1) {
        if (tid < o) hist[tid] = max(hist[tid], hist[tid + o]);
        __syncthreads();
    }
    if (tid == 0) {
        s_maxf = ord2f(hist[0]);
        s_kk = KTOP_;
        s_prefix = 0u;
    }
    __syncthreads();

    for (int level = 3; level >= 0; level--) {
        hist[tid] = 0u;
        __syncthreads();
        int shift = level * 8;
        unsigned maskhi = (level == 3) ? 0u : (0xFFFFFFFFu << (shift + 8));
        unsigned prefix = s_prefix;
        for (int i = tid; i < 4096; i += 256) {
            unsigned u = ua[i];
            if ((u & maskhi) == prefix)
                atomicAdd(&hist[(u >> shift) & 255], 1u);
        }
        __syncthreads();
        if (tid == 0) {
            int kk = s_kk;
            unsigned cum = 0;
            int d = 255;
            for (; d >= 0; d--) {
                unsigned c = hist[d];
                if (cum + c >= (unsigned)kk) break;
                cum += c;
            }
            if (d < 0) d = 0;
            s_kk = kk - (int)cum;
            s_prefix = prefix | ((unsigned)d << shift);
        }
        __syncthreads();
    }

    unsigned thr = s_prefix;
    float maxf = s_maxf;

    float ssum = 0.f;
    for (int i = tid; i < 4096; i += 256) {
        unsigned u = ua[i];
        if (u >= thr) ssum += expf(ord2f(u) - maxf);
    }
    redf[tid] = ssum;
    __syncthreads();
    for (int o = 128; o > 0; o >>= 1) {
        if (tid < o) redf[tid] += redf[tid + o];
        __syncthreads();
    }
    float inv = 1.f / redf[0];

    for (int i = tid * 2; i < 4096; i += 512) {
        unsigned u0 = ua[i], u1 = ua[i + 1];
        float2 vv = *(const float2*)&V[base + i];
        float o0 = 0.f, o1 = 0.f;
        if (u0 >= thr) o0 = vv.x * expf(ord2f(u0) - maxf) * inv;
        if (u1 >= thr) o1 = vv.y * expf(ord2f(u1) - maxf) * inv;
        __nv_bfloat162 h2 = __floats2bfloat162_rn(o0, o1);
        __nv_bfloat162 l2 = __floats2bfloat162_rn(o0 - __bfloat162float(h2.x),
                                                  o1 - __bfloat162float(h2.y));
        *(__nv_bfloat162*)&Hout[base + i] = h2;
        *(__nv_bfloat162*)&Lout[base + i] = l2;
    }
}

// ---------------- launch ----------------
extern "C" void kernel_launch(void* const* d_in, const int* in_sizes, int n_in,
                              void* d_out, int out_size)
{
    const float* x     = (const float*)d_in[0];
    const float* gamma = (const float*)d_in[1];
    const float* beta  = (const float*)d_in[2];
    const float* wq    = (const float*)d_in[3];
    const float* bq    = (const float*)d_in[4];
    const float* wk    = (const float*)d_in[5];
    const float* bk    = (const float*)d_in[6];
    const float* wv    = (const float*)d_in[7];
    const float* bv    = (const float*)d_in[8];
    const float* wf    = (const float*)d_in[9];
    const float* bf    = (const float*)d_in[10];
    float* out = (float*)d_out;

    void *pxn, *pxnh, *pxnl, *pq, *pk, *pv, *pf4h, *pf4l;
    void *pwkh, *pwkl, *pwqh, *pwql, *pwvh, *pwvl, *pwfh, *pwfl;
    cudaGetSymbolAddress(&pxn,  g_xn);
    cudaGetSymbolAddress(&pxnh, g_xnh);
    cudaGetSymbolAddress(&pxnl, g_xnl);
    cudaGetSymbolAddress(&pq,   g_q);
    cudaGetSymbolAddress(&pk,   g_k);
    cudaGetSymbolAddress(&pv,   g_v);
    cudaGetSymbolAddress(&pf4h, g_f4h);
    cudaGetSymbolAddress(&pf4l, g_f4l);
    cudaGetSymbolAddress(&pwkh, g_wkh);
    cudaGetSymbolAddress(&pwkl, g_wkl);
    cudaGetSymbolAddress(&pwqh, g_wqh);
    cudaGetSymbolAddress(&pwql, g_wql);
    cudaGetSymbolAddress(&pwvh, g_wvh);
    cudaGetSymbolAddress(&pwvl, g_wvl);
    cudaGetSymbolAddress(&pwfh, g_wfh);
    cudaGetSymbolAddress(&pwfl, g_wfl);

    cudaFuncSetAttribute(fft_attn_packed,
                         cudaFuncAttributeMaxDynamicSharedMemorySize, FFT2_SMEM_BYTES);

    // 0. weight split prep (tiled bf16 hi/lo)
    wsplit_kernel<<<36,  256>>>(wq, (__nv_bfloat16*)pwqh, (__nv_bfloat16*)pwql, 384);
    wsplit_kernel<<<36,  256>>>(wv, (__nv_bfloat16*)pwvh, (__nv_bfloat16*)pwvl, 384);
    wsplit_kernel<<<36,  256>>>(wf, (__nv_bfloat16*)pwfh, (__nv_bfloat16*)pwfl, 384);
    wsplit_kernel<<<324, 256>>>(wk, (__nv_bfloat16*)pwkh, (__nv_bfloat16*)pwkl, 3456);

    // 1. GroupNorm (+ bf16 hi/lo planes)
    groupnorm_kernel<<<B_ * NG_, 256>>>(x, gamma, beta);

    // 2-4. q / v (1x1) and k (3x3) projections
    dim3 gg(HW_ / 128, C_ / 128, B_);
    gemm_bf16_kernel<C_, false, false><<<gg, 256>>>(
        (const __nv_bfloat16*)pwqh, (const __nv_bfloat16*)pwql,
        (const __nv_bfloat16*)pxnh, (const __nv_bfloat16*)pxnl,
        (const float*)pxn, bq, (float*)pq);
    gemm_bf16_kernel<C_, false, false><<<gg, 256>>>(
        (const __nv_bfloat16*)pwvh, (const __nv_bfloat16*)pwvl,
        (const __nv_bfloat16*)pxnh, (const __nv_bfloat16*)pxnl,
        (const float*)pxn, bv, (float*)pv);
    gemm_bf16_kernel<C_ * 9, true, false><<<gg, 256>>>(
        (const __nv_bfloat16*)pwkh, (const __nv_bfloat16*)pwkl,
        (const __nv_bfloat16*)pxnh, (const __nv_bfloat16*)pxnl,
        (const float*)pxn, bk, (float*)pk);

    // 5. packed FFT circular conv: A (into g_q)
    fft_attn_packed<<<B_ * C_, 512, FFT2_SMEM_BYTES>>>((float*)pq, (const float*)pk);

    // 6. top-k + softmax + v-mul -> bf16 hi/lo F4 planes
    topk_softmax_kernel<<<B_ * C_, 256>>>((const float*)pq, (const float*)pv,
                                          (__nv_bfloat16*)pf4h, (__nv_bfloat16*)pf4l);

    // 7. final 1x1 conv with xn-multiply epilogue
    gemm_bf16_kernel<C_, false, true><<<gg, 256>>>(
        (const __nv_bfloat16*)pwfh, (const __nv_bfloat16*)pwfl,
        (const __nv_bfloat16*)pf4h, (const __nv_bfloat16*)pf4l,
        (const float*)pxn, bf, out);
}